// round 8
// baseline (speedup 1.0000x reference)
#include <cuda_runtime.h>
#include <cstddef>

// Problem constants
#define Dd   32
#define Ss   8
#define Oo   4
#define Tt   256
#define Bb   1024
#define ROWS 8            // batch rows per CTA -> 128 CTAs (one per SM, single wave)
#define NTHR 256          // thread = (d = tid>>3, slot = (tid>>1)&3, h = tid&1); 2 rows/thread matvec,
                          // each thread FINALIZES one row: h0 -> slot, h1 -> slot+4
#define ST   36           // padded row stride (floats) -> conflict-free smem
#define MS   (32*ST)      // floats per 32x32 matrix (padded)
#define RS   (ROWS*ST)    // floats per state buffer
#define NMAT 23

// smem float offsets
#define SM_ENC  (NMAT*MS)
#define SM_PHI  (SM_ENC + 32*8)
#define SM_BIAS (SM_PHI + 4*ST)
#define SM_ST   (SM_BIAS + 292)
#define SM_RI   (SM_ST + 6*RS)
#define SM_TOT  (SM_RI + RS)

// matrix slot order in smem:
// 0 wW 1 wI 2 wA | 3 att1 4 att2 | 5 wmg1 6 wmg2 | 7 zW 8 zI 9 zA |
// 10 rW 11 rIm 12 rA | 13 hW 14 hI 15 hA | 16 img1 17 img2 |
// 18 aW 19 aI 20 aA | 21 amg1 22 amg2

typedef unsigned long long u64;

struct Params {
    const float* obs;
    const float* enc_w;
    const float* sq[NMAT];
    int          rs[NMAT];
    const float* bv[9];
    const float* phi_w;
    const float* phi_b;
    float*       out;
};

__device__ __forceinline__ u64 f2fma(u64 a, u64 b, u64 c) {
    u64 d;
    asm("fma.rn.f32x2 %0, %1, %2, %3;" : "=l"(d) : "l"(a), "l"(b), "l"(c));
    return d;
}
__device__ __forceinline__ u64 f2add(u64 a, u64 b) {
    u64 d;
    asm("add.rn.f32x2 %0, %1, %2;" : "=l"(d) : "l"(a), "l"(b));
    return d;
}
__device__ __forceinline__ float psum(u64 a) {
    float lo = __uint_as_float((unsigned)(a & 0xffffffffull));
    float hi = __uint_as_float((unsigned)(a >> 32));
    return lo + hi;
}
// Exchange-reduce: keep own-row partial, swap other-row partial with h-partner.
__device__ __forceinline__ float redu2(u64 x0, u64 x1, int h, float bias) {
    float s0 = psum(x0);
    float s1 = psum(x1);
    float send = h ? s0 : s1;
    float own  = h ? s1 : s0;
    float recv = __shfl_xor_sync(0xffffffffu, send, 1);
    return own + recv + bias;
}
__device__ __forceinline__ float sigm(float x) {
    return __fdividef(1.f, 1.f + __expf(-x));
}
__device__ __forceinline__ float tanh_f(float x) {
    return 1.f - __fdividef(2.f, __expf(2.f * x) + 1.f);
}
__device__ __forceinline__ ulonglong2 ld2(const float* p) {
    return *(const ulonglong2*)p;
}
#define ACC2(acc, w, v) do { acc = f2fma((w).x, (v).x, acc); acc = f2fma((w).y, (v).y, acc); } while (0)

__global__ __launch_bounds__(NTHR, 1)
void anima_kernel(const Params p) {
    extern __shared__ float sm[];
    const int tid = threadIdx.x;

    // ---- cooperative weight load into padded smem ----
    #pragma unroll 1
    for (int m = 0; m < NMAT; m++) {
        const float* src = p.sq[m];
        const int rstr = p.rs[m];
        float* dst = sm + m * MS;
        #pragma unroll 1
        for (int i = tid; i < 1024; i += NTHR)
            dst[(i >> 5) * ST + (i & 31)] = src[(i >> 5) * rstr + (i & 31)];
    }
    sm[SM_ENC + tid] = p.enc_w[tid];   // 32x8 compact
    if (tid < 128)
        sm[SM_PHI + (tid >> 5) * ST + (tid & 31)] = p.phi_w[tid];
    if (tid < 32) {
        #pragma unroll
        for (int j = 0; j < 9; j++)
            sm[SM_BIAS + j * 32 + tid] = p.bv[j][tid];
        if (tid < 4) sm[SM_BIAS + 288 + tid] = p.phi_b[tid];
    }
    #pragma unroll 1
    for (int i = tid; i < 7 * RS; i += NTHR)
        sm[SM_ST + i] = 0.f;
    __syncthreads();

    const int d    = tid >> 3;
    const int slot = (tid >> 1) & 3;
    const int h    = tid & 1;
    const int kb   = h * 16;
    const int rb0  = slot * ST;
    const int rb1  = (slot + 4) * ST;
    const int rbo  = h ? rb1 : rb0;        // owned row base
    const int row0 = blockIdx.x * ROWS;
    const long gro = row0 + slot + (h ? 4 : 0);   // owned global row
    const float* wd = sm + d * ST + kb;

    float* Wc = sm + SM_ST;      float* Wn = Wc + RS;
    float* Ic = Wn + RS;         float* In = Ic + RS;
    float* Ac = In + RS;         float* An = Ac + RS;
    float* RI = sm + SM_RI;

    const float attb = sm[SM_BIAS +   0 + d];
    const float wmgb = sm[SM_BIAS +  32 + d];
    const float imgb = sm[SM_BIAS +  64 + d];
    const float amgb = sm[SM_BIAS +  96 + d];
    const float zb   = sm[SM_BIAS + 128 + d];
    const float rbi  = sm[SM_BIAS + 160 + d];
    const float hbi  = sm[SM_BIAS + 192 + d];
    const float abi  = sm[SM_BIAS + 224 + d];
    const float encb = sm[SM_BIAS + 256 + d];
    const float phib = (d < Oo) ? sm[SM_BIAS + 288 + d] : 0.f;

    const ulonglong2 encA = ld2(sm + SM_ENC + d * 8);
    const ulonglong2 encB = ld2(sm + SM_ENC + d * 8 + 4);

    #define WL(m, c) ld2(wd + (m) * MS + (c) * 4)

    // hI (matrix 14) weights cached in registers for all steps (constant)
    const ulonglong2 whi0 = WL(14, 0), whi1 = WL(14, 1),
                     whi2 = WL(14, 2), whi3 = WL(14, 3);

    u64 icache[2][8];   // old I, this k-half, rows {slot, slot+4} (live in phase 1 only)
    u64 acache[2][8];   // old A (live in phase 1 only)

    #pragma unroll 1
    for (int t = 0; t < Tt; t++) {
        // obs: own row only
        const float* ob = p.obs + ((size_t)t * Bb + gro) * Ss;
        ulonglong2 oa = *(const ulonglong2*)(ob);
        ulonglong2 obv = *(const ulonglong2*)(ob + 4);

        // ======== PHASE-1 BLOCK: phase-1 matvec + ALL old-I/old-A chains of later phases ========
        u64 w_w0 = 0, w_i0 = 0, w_a0 = 0, w_w1 = 0, w_i1 = 0, w_a1 = 0;
        u64 at_w0 = 0, at_i0 = 0, at_w1 = 0, at_i1 = 0;
        u64 mg_i0 = 0, mg_a0 = 0, mg_i1 = 0, mg_a1 = 0;
        #pragma unroll
        for (int c = 0; c < 4; c++) {
            const int ko = kb + c * 4;
            ulonglong2 w0 = WL(0, c), w1 = WL(1, c), w2 = WL(2, c);
            ulonglong2 w3 = WL(3, c), w4 = WL(4, c), w5 = WL(5, c), w6 = WL(6, c);
            ulonglong2 Wv0 = ld2(Wc + rb0 + ko), Wv1 = ld2(Wc + rb1 + ko);
            ulonglong2 Iv0 = ld2(Ic + rb0 + ko), Iv1 = ld2(Ic + rb1 + ko);
            ulonglong2 Av0 = ld2(Ac + rb0 + ko), Av1 = ld2(Ac + rb1 + ko);
            icache[0][2*c] = Iv0.x; icache[0][2*c+1] = Iv0.y;
            icache[1][2*c] = Iv1.x; icache[1][2*c+1] = Iv1.y;
            acache[0][2*c] = Av0.x; acache[0][2*c+1] = Av0.y;
            acache[1][2*c] = Av1.x; acache[1][2*c+1] = Av1.y;
            ACC2(w_w0, w0, Wv0);   ACC2(w_w1, w0, Wv1);
            ACC2(w_i0, w1, Iv0);   ACC2(w_i1, w1, Iv1);
            ACC2(w_a0, w2, Av0);   ACC2(w_a1, w2, Av1);
            ACC2(at_w0, w3, Wv0);  ACC2(at_w1, w3, Wv1);
            ACC2(at_i0, w4, Iv0);  ACC2(at_i1, w4, Iv1);
            ACC2(mg_i0, w5, Iv0);  ACC2(mg_i1, w5, Iv1);
            ACC2(mg_a0, w6, Av0);  ACC2(mg_a1, w6, Av1);
        }
        // early chains for phases 2 & 4 that need only OLD I / OLD A (fills phase-1 tail stalls)
        u64 z_i0 = 0, z_i1 = 0, z_a0 = 0, z_a1 = 0;
        u64 r_i0 = 0, r_i1 = 0, r_a0 = 0, r_a1 = 0;
        u64 h_a0 = 0, h_a1 = 0, mi_a0 = 0, mi_a1 = 0;
        u64 a_a0 = 0, a_a1 = 0;
        #pragma unroll
        for (int c = 0; c < 4; c++) {
            ulonglong2 w8 = WL(8, c),  w9 = WL(9, c);
            ulonglong2 wb = WL(11, c), wc = WL(12, c);
            ulonglong2 wf = WL(15, c), wh = WL(17, c);
            ulonglong2 wt = WL(20, c);
            ulonglong2 Iv0 = { icache[0][2*c], icache[0][2*c+1] };
            ulonglong2 Iv1 = { icache[1][2*c], icache[1][2*c+1] };
            ulonglong2 Av0 = { acache[0][2*c], acache[0][2*c+1] };
            ulonglong2 Av1 = { acache[1][2*c], acache[1][2*c+1] };
            ACC2(z_i0, w8, Iv0);   ACC2(z_i1, w8, Iv1);
            ACC2(z_a0, w9, Av0);   ACC2(z_a1, w9, Av1);
            ACC2(r_i0, wb, Iv0);   ACC2(r_i1, wb, Iv1);
            ACC2(r_a0, wc, Av0);   ACC2(r_a1, wc, Av1);
            ACC2(h_a0, wf, Av0);   ACC2(h_a1, wf, Av1);
            ACC2(mi_a0, wh, Av0);  ACC2(mi_a1, wh, Av1);
            ACC2(a_a0, wt, Av0);   ACC2(a_a1, wt, Av1);
        }
        // phase-1 tail
        float sW  = redu2(f2add(f2add(w_w0, w_i0), w_a0),
                          f2add(f2add(w_w1, w_i1), w_a1), h, 0.f);
        float sAt = redu2(f2add(at_w0, at_i0), f2add(at_w1, at_i1), h, attb);
        float sMg = redu2(f2add(mg_i0, mg_a0), f2add(mg_i1, mg_a1), h, wmgb);
        u64 e = f2fma(encA.x, oa.x, 0ull);
        e = f2fma(encA.y, oa.y, e);
        u64 eb = f2fma(encB.x, obv.x, 0ull);
        eb = f2fma(encB.y, obv.y, eb);
        float oe = tanh_f(encb + psum(f2add(e, eb)));
        float wnew = tanh_f(oe * sigm(sAt) + sW * sigm(sMg));
        Wn[rbo + d] = wnew;
        __syncthreads();

        // ======== PHASE-2 BLOCK: Wn-dependent chains of phases 2 AND 4 ========
        u64 z_w0 = 0, z_w1 = 0, r_w0 = 0, r_w1 = 0;
        u64 h_w0 = 0, h_w1 = 0, mi_w0 = 0, mi_w1 = 0;
        u64 a_w0 = 0, a_w1 = 0, ma_w0 = 0, ma_w1 = 0;   // phase-4 precompute
        #pragma unroll
        for (int c = 0; c < 4; c++) {
            const int ko = kb + c * 4;
            ulonglong2 Wv0 = ld2(Wn + rb0 + ko), Wv1 = ld2(Wn + rb1 + ko);
            ulonglong2 w7 = WL(7, c),  wa = WL(10, c);
            ulonglong2 we = WL(13, c), wg = WL(16, c);
            ulonglong2 wi = WL(18, c), wl = WL(21, c);
            ACC2(z_w0, w7, Wv0);   ACC2(z_w1, w7, Wv1);
            ACC2(r_w0, wa, Wv0);   ACC2(r_w1, wa, Wv1);
            ACC2(h_w0, we, Wv0);   ACC2(h_w1, we, Wv1);
            ACC2(mi_w0, wg, Wv0);  ACC2(mi_w1, wg, Wv1);
            ACC2(a_w0, wi, Wv0);   ACC2(a_w1, wi, Wv1);
            ACC2(ma_w0, wl, Wv0);  ACC2(ma_w1, wl, Wv1);
        }
        float z  = sigm(redu2(f2add(f2add(z_w0, z_i0), z_a0),
                              f2add(f2add(z_w1, z_i1), z_a1), h, zb));
        float rg = sigm(redu2(f2add(f2add(r_w0, r_i0), r_a0),
                              f2add(f2add(r_w1, r_i1), r_a1), h, rbi));
        float mi = sigm(redu2(f2add(mi_w0, mi_a0), f2add(mi_w1, mi_a1), h, imgb));
        float Iold = Ic[rbo + d];
        RI[rbo + d] = rg * Iold;
        u64 hacc0 = f2add(h_w0, h_a0);
        u64 hacc1 = f2add(h_w1, h_a1);
        __syncthreads();

        // ======== PHASE 3: h = tanh(hpart + hI*(r.I)); I_new ========
        u64 hr0 = 0, hr1 = 0;
        {
            ulonglong2 R0, R1;
            R0 = ld2(RI + rb0 + kb);      R1 = ld2(RI + rb1 + kb);
            ACC2(hr0, whi0, R0);          ACC2(hr1, whi0, R1);
            R0 = ld2(RI + rb0 + kb + 4);  R1 = ld2(RI + rb1 + kb + 4);
            ACC2(hr0, whi1, R0);          ACC2(hr1, whi1, R1);
            R0 = ld2(RI + rb0 + kb + 8);  R1 = ld2(RI + rb1 + kb + 8);
            ACC2(hr0, whi2, R0);          ACC2(hr1, whi2, R1);
            R0 = ld2(RI + rb0 + kb + 12); R1 = ld2(RI + rb1 + kb + 12);
            ACC2(hr0, whi3, R0);          ACC2(hr1, whi3, R1);
        }
        float hv = tanh_f(redu2(f2add(hacc0, hr0), f2add(hacc1, hr1), h, hbi));
        float inew = (1.f - z) * Iold + z * (hv * mi);
        In[rbo + d] = inew;
        __syncthreads();

        // ======== PHASE 4 (small): only In-dependent chains remain ========
        u64 a_i0 = 0, a_i1 = 0, ma_i0 = 0, ma_i1 = 0;
        #pragma unroll
        for (int c = 0; c < 4; c++) {
            const int ko = kb + c * 4;
            ulonglong2 Nv0 = ld2(In + rb0 + ko), Nv1 = ld2(In + rb1 + ko);
            ulonglong2 wj = WL(19, c), wm = WL(22, c);
            ACC2(a_i0, wj, Nv0);   ACC2(a_i1, wj, Nv1);
            ACC2(ma_i0, wm, Nv0);  ACC2(ma_i1, wm, Nv1);
        }
        float sA  = redu2(f2add(f2add(a_w0, a_i0), a_a0),
                          f2add(f2add(a_w1, a_i1), a_a1), h, abi);
        float sMa = redu2(f2add(ma_w0, ma_i0), f2add(ma_w1, ma_i1), h, amgb);
        float anew = tanh_f(sA * sigm(sMa));
        An[rbo + d] = anew;
        __syncthreads();

        // ---- output: actions = phi(A_new); d<4 -> warp 0 ----
        if (d < Oo) {
            u64 aO0 = 0, aO1 = 0;
            #pragma unroll
            for (int c = 0; c < 4; c++) {
                const int ko = kb + c * 4;
                ulonglong2 pw = ld2(sm + SM_PHI + d * ST + ko);
                ulonglong2 A0 = ld2(An + rb0 + ko), A1 = ld2(An + rb1 + ko);
                ACC2(aO0, pw, A0);
                ACC2(aO1, pw, A1);
            }
            float o = redu2(aO0, aO1, h, phib);
            p.out[((size_t)t * Bb + gro) * Oo + d] = o;
        }

        // rotate state buffers
        float* tmp;
        tmp = Wc; Wc = Wn; Wn = tmp;
        tmp = Ic; Ic = In; In = tmp;
        tmp = Ac; Ac = An; An = tmp;
    }
    #undef WL
}

extern "C" void kernel_launch(void* const* d_in, const int* in_sizes, int n_in,
                              void* d_out, int out_size) {
    const float* const* in = (const float* const*)d_in;
    const float *obs, *enc_w, *enc_b;
    const float *wW, *wI, *wA, *zW, *zI, *zA, *rW, *rIm, *rA, *hW, *hI, *hA, *aW, *aI, *aA;
    const float *att_w, *att_b, *wmg_w, *wmg_b, *img_w, *img_b, *amg_w, *amg_b;
    const float *z_b, *r_b, *h_b, *a_b, *phi_w, *phi_b;

    if (in_sizes[6] == 2048) {
        obs = in[0]; enc_w = in[1]; enc_b = in[2];
        wW = in[3]; wI = in[4]; wA = in[5];
        att_w = in[6]; att_b = in[7]; wmg_w = in[8]; wmg_b = in[9];
        zW = in[10]; zI = in[11]; zA = in[12]; z_b = in[13];
        rW = in[14]; rIm = in[15]; rA = in[16]; r_b = in[17];
        hW = in[18]; hI = in[19]; hA = in[20]; h_b = in[21];
        img_w = in[22]; img_b = in[23];
        aW = in[24]; aI = in[25]; aA = in[26]; a_b = in[27];
        amg_w = in[28]; amg_b = in[29];
        phi_w = in[30]; phi_b = in[31];
    } else {
        obs = in[0]; enc_w = in[1]; enc_b = in[2];
        wW = in[3]; wI = in[4]; wA = in[5];
        zW = in[6]; zI = in[7]; zA = in[8];
        rW = in[9]; rIm = in[10]; rA = in[11];
        hW = in[12]; hI = in[13]; hA = in[14];
        aW = in[15]; aI = in[16]; aA = in[17];
        att_w = in[18]; att_b = in[19];
        wmg_w = in[20]; wmg_b = in[21];
        img_w = in[22]; img_b = in[23];
        amg_w = in[24]; amg_b = in[25];
        z_b = in[26]; r_b = in[27]; h_b = in[28]; a_b = in[29];
        phi_w = in[30]; phi_b = in[31];
    }

    Params p;
    p.obs = obs; p.enc_w = enc_w;
    const float* sq[NMAT] = {
        wW, wI, wA,
        att_w, att_w + 32,
        wmg_w, wmg_w + 32,
        zW, zI, zA,
        rW, rIm, rA,
        hW, hI, hA,
        img_w, img_w + 32,
        aW, aI, aA,
        amg_w, amg_w + 32
    };
    const int rs[NMAT] = {
        32, 32, 32,
        64, 64,
        64, 64,
        32, 32, 32,
        32, 32, 32,
        32, 32, 32,
        64, 64,
        32, 32, 32,
        64, 64
    };
    for (int i = 0; i < NMAT; i++) { p.sq[i] = sq[i]; p.rs[i] = rs[i]; }
    const float* bv[9] = { att_b, wmg_b, img_b, amg_b, z_b, r_b, h_b, a_b, enc_b };
    for (int i = 0; i < 9; i++) p.bv[i] = bv[i];
    p.phi_w = phi_w; p.phi_b = phi_b;
    p.out = (float*)d_out;

    const int smemBytes = SM_TOT * (int)sizeof(float);
    cudaFuncSetAttribute(anima_kernel,
                         cudaFuncAttributeMaxDynamicSharedMemorySize, smemBytes);
    anima_kernel<<<Bb / ROWS, NTHR, smemBytes>>>(p);
}

// round 11
// speedup vs baseline: 1.0738x; 1.0738x over previous
#include <cuda_runtime.h>
#include <cstddef>

// Problem constants
#define Dd   32
#define Ss   8
#define Oo   4
#define Tt   256
#define Bb   1024
#define ROWS 8            // batch rows per CTA -> 128 CTAs (one per SM, single wave)
#define NTHR 256          // TWO independent groups of 128 threads:
                          //   group g (tid>>7) owns rows 4g..4g+3, synced by bar.sync g+1,128
                          // within group: t=tid&127, d=t>>2, s=(t>>1)&1, h=t&1
                          //   thread matvecs rows {4g+s, 4g+s+2}, owns (finalizes) row 4g+s+2h
#define ST   36           // padded row stride (floats) -> conflict-free smem
#define MS   (32*ST)      // floats per 32x32 matrix (padded)
#define RS   (ROWS*ST)    // floats per state buffer
#define NMAT 23

// smem float offsets
#define SM_ENC  (NMAT*MS)
#define SM_PHI  (SM_ENC + 32*8)
#define SM_BIAS (SM_PHI + 4*ST)
#define SM_ST   (SM_BIAS + 292)
#define SM_RI   (SM_ST + 6*RS)
#define SM_TOT  (SM_RI + RS)

// matrix slot order in smem:
// 0 wW 1 wI 2 wA | 3 att1 4 att2 | 5 wmg1 6 wmg2 | 7 zW 8 zI 9 zA |
// 10 rW 11 rIm 12 rA | 13 hW 14 hI 15 hA | 16 img1 17 img2 |
// 18 aW 19 aI 20 aA | 21 amg1 22 amg2

typedef unsigned long long u64;

struct Params {
    const float* obs;
    const float* enc_w;
    const float* sq[NMAT];
    int          rs[NMAT];
    const float* bv[9];
    const float* phi_w;
    const float* phi_b;
    float*       out;
};

__device__ __forceinline__ u64 f2fma(u64 a, u64 b, u64 c) {
    u64 d;
    asm("fma.rn.f32x2 %0, %1, %2, %3;" : "=l"(d) : "l"(a), "l"(b), "l"(c));
    return d;
}
__device__ __forceinline__ u64 f2add(u64 a, u64 b) {
    u64 d;
    asm("add.rn.f32x2 %0, %1, %2;" : "=l"(d) : "l"(a), "l"(b));
    return d;
}
__device__ __forceinline__ float psum(u64 a) {
    float lo = __uint_as_float((unsigned)(a & 0xffffffffull));
    float hi = __uint_as_float((unsigned)(a >> 32));
    return lo + hi;
}
// Exchange-reduce: keep own-row partial, swap other-row partial with h-partner (lane^1).
// mask must name exactly the converged lanes executing this call.
__device__ __forceinline__ float redu2(u64 x0, u64 x1, int h, float bias, unsigned mask) {
    float s0 = psum(x0);
    float s1 = psum(x1);
    float send = h ? s0 : s1;
    float own  = h ? s1 : s0;
    float recv = __shfl_xor_sync(mask, send, 1);
    return own + recv + bias;
}
__device__ __forceinline__ float sigm(float x) {
    return __fdividef(1.f, 1.f + __expf(-x));
}
__device__ __forceinline__ float tanh_f(float x) {
    return 1.f - __fdividef(2.f, __expf(2.f * x) + 1.f);
}
__device__ __forceinline__ ulonglong2 ld2(const float* p) {
    return *(const ulonglong2*)p;
}
__device__ __forceinline__ void gsync(int bar) {
    asm volatile("bar.sync %0, %1;" :: "r"(bar), "r"(128) : "memory");
}
#define ACC2(acc, w, v) do { acc = f2fma((w).x, (v).x, acc); acc = f2fma((w).y, (v).y, acc); } while (0)
#define FULLM 0xffffffffu

__global__ __launch_bounds__(NTHR, 1)
void anima_kernel(const Params p) {
    extern __shared__ float sm[];
    const int tid = threadIdx.x;

    // ---- cooperative weight load into padded smem (whole CTA) ----
    #pragma unroll 1
    for (int m = 0; m < NMAT; m++) {
        const float* src = p.sq[m];
        const int rstr = p.rs[m];
        float* dst = sm + m * MS;
        #pragma unroll 1
        for (int i = tid; i < 1024; i += NTHR)
            dst[(i >> 5) * ST + (i & 31)] = src[(i >> 5) * rstr + (i & 31)];
    }
    sm[SM_ENC + tid] = p.enc_w[tid];   // 32x8 compact
    if (tid < 128)
        sm[SM_PHI + (tid >> 5) * ST + (tid & 31)] = p.phi_w[tid];
    if (tid < 32) {
        #pragma unroll
        for (int j = 0; j < 9; j++)
            sm[SM_BIAS + j * 32 + tid] = p.bv[j][tid];
        if (tid < 4) sm[SM_BIAS + 288 + tid] = p.phi_b[tid];
    }
    #pragma unroll 1
    for (int i = tid; i < 7 * RS; i += NTHR)
        sm[SM_ST + i] = 0.f;
    __syncthreads();

    const int gid  = tid >> 7;             // barrier group 0/1 -> rows 4g..4g+3
    const int bar  = gid + 1;              // named barrier id
    const int t7   = tid & 127;
    const int d    = t7 >> 2;              // 0..31
    const int s    = (t7 >> 1) & 1;        // row sub-slot
    const int h    = t7 & 1;               // k-half; owns row (4g+s+2h)
    const int kb   = h * 16;
    const int rb0  = (4 * gid + s) * ST;
    const int rb1  = rb0 + 2 * ST;
    const int rbo  = h ? rb1 : rb0;        // owned row base
    const int row0 = blockIdx.x * ROWS;
    const long gro = row0 + 4 * gid + s + 2 * h;   // owned global row
    const float* wd = sm + d * ST + kb;

    float* Wc = sm + SM_ST;      float* Wn = Wc + RS;
    float* Ic = Wn + RS;         float* In = Ic + RS;
    float* Ac = In + RS;         float* An = Ac + RS;
    float* RI = sm + SM_RI;

    const float attb = sm[SM_BIAS +   0 + d];
    const float wmgb = sm[SM_BIAS +  32 + d];
    const float imgb = sm[SM_BIAS +  64 + d];
    const float amgb = sm[SM_BIAS +  96 + d];
    const float zb   = sm[SM_BIAS + 128 + d];
    const float rbi  = sm[SM_BIAS + 160 + d];
    const float hbi  = sm[SM_BIAS + 192 + d];
    const float abi  = sm[SM_BIAS + 224 + d];
    const float encb = sm[SM_BIAS + 256 + d];
    const float phib = (d < Oo) ? sm[SM_BIAS + 288 + d] : 0.f;

    const ulonglong2 encA = ld2(sm + SM_ENC + d * 8);
    const ulonglong2 encB = ld2(sm + SM_ENC + d * 8 + 4);

    #define WL(m, c) ld2(wd + (m) * MS + (c) * 4)

    // hI (matrix 14) weights cached in registers for all steps (constant)
    const ulonglong2 whi0 = WL(14, 0), whi1 = WL(14, 1),
                     whi2 = WL(14, 2), whi3 = WL(14, 3);

    u64 icache[2][8];   // old I, this k-half, rows {rb0, rb1}
    u64 acache[2][8];   // old A
    u64 wcache[2][8];   // W_new (cached phase2 -> phase4)

    #pragma unroll 1
    for (int t = 0; t < Tt; t++) {
        // obs: own row only
        const float* ob = p.obs + ((size_t)t * Bb + gro) * Ss;
        ulonglong2 oa = *(const ulonglong2*)(ob);
        ulonglong2 obv = *(const ulonglong2*)(ob + 4);

        // ---- phase 1: W_all, attn, wmg, obs_enc -> W_new ----
        u64 w_w0 = 0, w_i0 = 0, w_a0 = 0, w_w1 = 0, w_i1 = 0, w_a1 = 0;
        u64 at_w0 = 0, at_i0 = 0, at_w1 = 0, at_i1 = 0;
        u64 mg_i0 = 0, mg_a0 = 0, mg_i1 = 0, mg_a1 = 0;
        #pragma unroll
        for (int c = 0; c < 4; c++) {
            const int ko = kb + c * 4;
            ulonglong2 w0 = WL(0, c), w1 = WL(1, c), w2 = WL(2, c);
            ulonglong2 w3 = WL(3, c), w4 = WL(4, c), w5 = WL(5, c), w6 = WL(6, c);
            ulonglong2 Wv0 = ld2(Wc + rb0 + ko), Wv1 = ld2(Wc + rb1 + ko);
            ulonglong2 Iv0 = ld2(Ic + rb0 + ko), Iv1 = ld2(Ic + rb1 + ko);
            ulonglong2 Av0 = ld2(Ac + rb0 + ko), Av1 = ld2(Ac + rb1 + ko);
            icache[0][2*c] = Iv0.x; icache[0][2*c+1] = Iv0.y;
            icache[1][2*c] = Iv1.x; icache[1][2*c+1] = Iv1.y;
            acache[0][2*c] = Av0.x; acache[0][2*c+1] = Av0.y;
            acache[1][2*c] = Av1.x; acache[1][2*c+1] = Av1.y;
            ACC2(w_w0, w0, Wv0);   ACC2(w_w1, w0, Wv1);
            ACC2(w_i0, w1, Iv0);   ACC2(w_i1, w1, Iv1);
            ACC2(w_a0, w2, Av0);   ACC2(w_a1, w2, Av1);
            ACC2(at_w0, w3, Wv0);  ACC2(at_w1, w3, Wv1);
            ACC2(at_i0, w4, Iv0);  ACC2(at_i1, w4, Iv1);
            ACC2(mg_i0, w5, Iv0);  ACC2(mg_i1, w5, Iv1);
            ACC2(mg_a0, w6, Av0);  ACC2(mg_a1, w6, Av1);
        }
        float sW  = redu2(f2add(f2add(w_w0, w_i0), w_a0),
                          f2add(f2add(w_w1, w_i1), w_a1), h, 0.f, FULLM);
        float sAt = redu2(f2add(at_w0, at_i0), f2add(at_w1, at_i1), h, attb, FULLM);
        float sMg = redu2(f2add(mg_i0, mg_a0), f2add(mg_i1, mg_a1), h, wmgb, FULLM);
        u64 e = f2fma(encA.x, oa.x, 0ull);
        e = f2fma(encA.y, oa.y, e);
        u64 eb = f2fma(encB.x, obv.x, 0ull);
        eb = f2fma(encB.y, obv.y, eb);
        float oe = tanh_f(encb + psum(f2add(e, eb)));
        float wnew = tanh_f(oe * sigm(sAt) + sW * sigm(sMg));
        Wn[rbo + d] = wnew;
        // prefetch phase-2 c=0 weights across the barrier (constant data, no hazard)
        ulonglong2 q7 = WL(7, 0),  q8 = WL(8, 0),  q9 = WL(9, 0);
        ulonglong2 qa = WL(10, 0), qb = WL(11, 0), qc = WL(12, 0);
        ulonglong2 qe = WL(13, 0), qf = WL(15, 0);
        ulonglong2 qg = WL(16, 0), qh = WL(17, 0);
        gsync(bar);

        // ---- phase 2: z, r, h-partial, mult_I ----
        u64 z_w0 = 0, z_i0 = 0, z_a0 = 0, z_w1 = 0, z_i1 = 0, z_a1 = 0;
        u64 r_w0 = 0, r_i0 = 0, r_a0 = 0, r_w1 = 0, r_i1 = 0, r_a1 = 0;
        u64 h_w0 = 0, h_a0 = 0, h_w1 = 0, h_a1 = 0;
        u64 mi_w0 = 0, mi_a0 = 0, mi_w1 = 0, mi_a1 = 0;
        #pragma unroll
        for (int c = 0; c < 4; c++) {
            const int ko = kb + c * 4;
            ulonglong2 Wv0 = ld2(Wn + rb0 + ko), Wv1 = ld2(Wn + rb1 + ko);
            wcache[0][2*c] = Wv0.x; wcache[0][2*c+1] = Wv0.y;
            wcache[1][2*c] = Wv1.x; wcache[1][2*c+1] = Wv1.y;
            ulonglong2 w7 = (c == 0) ? q7 : WL(7, c);
            ulonglong2 w8 = (c == 0) ? q8 : WL(8, c);
            ulonglong2 w9 = (c == 0) ? q9 : WL(9, c);
            ulonglong2 wa = (c == 0) ? qa : WL(10, c);
            ulonglong2 wb = (c == 0) ? qb : WL(11, c);
            ulonglong2 wc = (c == 0) ? qc : WL(12, c);
            ulonglong2 we = (c == 0) ? qe : WL(13, c);
            ulonglong2 wf = (c == 0) ? qf : WL(15, c);
            ulonglong2 wg = (c == 0) ? qg : WL(16, c);
            ulonglong2 wh = (c == 0) ? qh : WL(17, c);
            ulonglong2 Iv0 = { icache[0][2*c], icache[0][2*c+1] };
            ulonglong2 Iv1 = { icache[1][2*c], icache[1][2*c+1] };
            ulonglong2 Av0 = { acache[0][2*c], acache[0][2*c+1] };
            ulonglong2 Av1 = { acache[1][2*c], acache[1][2*c+1] };
            ACC2(z_w0, w7, Wv0);   ACC2(z_w1, w7, Wv1);
            ACC2(z_i0, w8, Iv0);   ACC2(z_i1, w8, Iv1);
            ACC2(z_a0, w9, Av0);   ACC2(z_a1, w9, Av1);
            ACC2(r_w0, wa, Wv0);   ACC2(r_w1, wa, Wv1);
            ACC2(r_i0, wb, Iv0);   ACC2(r_i1, wb, Iv1);
            ACC2(r_a0, wc, Av0);   ACC2(r_a1, wc, Av1);
            ACC2(h_w0, we, Wv0);   ACC2(h_w1, we, Wv1);
            ACC2(h_a0, wf, Av0);   ACC2(h_a1, wf, Av1);
            ACC2(mi_w0, wg, Wv0);  ACC2(mi_w1, wg, Wv1);
            ACC2(mi_a0, wh, Av0);  ACC2(mi_a1, wh, Av1);
        }
        float z  = sigm(redu2(f2add(f2add(z_w0, z_i0), z_a0),
                              f2add(f2add(z_w1, z_i1), z_a1), h, zb, FULLM));
        float rg = sigm(redu2(f2add(f2add(r_w0, r_i0), r_a0),
                              f2add(f2add(r_w1, r_i1), r_a1), h, rbi, FULLM));
        float mi = sigm(redu2(f2add(mi_w0, mi_a0), f2add(mi_w1, mi_a1), h, imgb, FULLM));
        float Iold = Ic[rbo + d];              // own row only
        RI[rbo + d] = rg * Iold;
        u64 hacc0 = f2add(h_w0, h_a0);
        u64 hacc1 = f2add(h_w1, h_a1);
        gsync(bar);

        // ---- phase 3: h = tanh(hpart + hI*(r.I)); I_new ----
        u64 hr0 = 0, hr1 = 0;
        {
            ulonglong2 R0, R1;
            R0 = ld2(RI + rb0 + kb);      R1 = ld2(RI + rb1 + kb);
            ACC2(hr0, whi0, R0);          ACC2(hr1, whi0, R1);
            R0 = ld2(RI + rb0 + kb + 4);  R1 = ld2(RI + rb1 + kb + 4);
            ACC2(hr0, whi1, R0);          ACC2(hr1, whi1, R1);
            R0 = ld2(RI + rb0 + kb + 8);  R1 = ld2(RI + rb1 + kb + 8);
            ACC2(hr0, whi2, R0);          ACC2(hr1, whi2, R1);
            R0 = ld2(RI + rb0 + kb + 12); R1 = ld2(RI + rb1 + kb + 12);
            ACC2(hr0, whi3, R0);          ACC2(hr1, whi3, R1);
        }
        float hv = tanh_f(redu2(f2add(hacc0, hr0), f2add(hacc1, hr1), h, hbi, FULLM));
        float inew = (1.f - z) * Iold + z * (hv * mi);
        In[rbo + d] = inew;
        // prefetch phase-4 c=0 weights across the barrier
        ulonglong2 qi = WL(18, 0), qj = WL(19, 0), qk = WL(20, 0);
        ulonglong2 ql = WL(21, 0), qm = WL(22, 0);
        gsync(bar);

        // ---- phase 4: A_all, mult_A -> A_new ----
        u64 a_w0 = 0, a_i0 = 0, a_a0 = 0, a_w1 = 0, a_i1 = 0, a_a1 = 0;
        u64 ma_w0 = 0, ma_i0 = 0, ma_w1 = 0, ma_i1 = 0;
        #pragma unroll
        for (int c = 0; c < 4; c++) {
            const int ko = kb + c * 4;
            ulonglong2 Wv0 = { wcache[0][2*c], wcache[0][2*c+1] };
            ulonglong2 Wv1 = { wcache[1][2*c], wcache[1][2*c+1] };
            ulonglong2 Nv0 = ld2(In + rb0 + ko), Nv1 = ld2(In + rb1 + ko);
            ulonglong2 Av0 = { acache[0][2*c], acache[0][2*c+1] };
            ulonglong2 Av1 = { acache[1][2*c], acache[1][2*c+1] };
            ulonglong2 wi = (c == 0) ? qi : WL(18, c);
            ulonglong2 wj = (c == 0) ? qj : WL(19, c);
            ulonglong2 wk = (c == 0) ? qk : WL(20, c);
            ulonglong2 wl = (c == 0) ? ql : WL(21, c);
            ulonglong2 wm = (c == 0) ? qm : WL(22, c);
            ACC2(a_w0, wi, Wv0);   ACC2(a_w1, wi, Wv1);
            ACC2(a_i0, wj, Nv0);   ACC2(a_i1, wj, Nv1);
            ACC2(a_a0, wk, Av0);   ACC2(a_a1, wk, Av1);
            ACC2(ma_w0, wl, Wv0);  ACC2(ma_w1, wl, Wv1);
            ACC2(ma_i0, wm, Nv0);  ACC2(ma_i1, wm, Nv1);
        }
        float sA  = redu2(f2add(f2add(a_w0, a_i0), a_a0),
                          f2add(f2add(a_w1, a_i1), a_a1), h, abi, FULLM);
        float sMa = redu2(f2add(ma_w0, ma_i0), f2add(ma_w1, ma_i1), h, amgb, FULLM);
        float anew = tanh_f(sA * sigm(sMa));
        An[rbo + d] = anew;
        gsync(bar);

        // ---- output: actions = phi(A_new); d<4 -> lanes 0..15 of warp 0 of each
        //      group: PARTIAL-WARP branch, so the shfl mask is 0xffff ----
        if (d < Oo) {
            u64 aO0 = 0, aO1 = 0;
            #pragma unroll
            for (int c = 0; c < 4; c++) {
                const int ko = kb + c * 4;
                ulonglong2 pw = ld2(sm + SM_PHI + d * ST + ko);
                ulonglong2 A0 = ld2(An + rb0 + ko), A1 = ld2(An + rb1 + ko);
                ACC2(aO0, pw, A0);
                ACC2(aO1, pw, A1);
            }
            float o = redu2(aO0, aO1, h, phib, 0x0000ffffu);
            p.out[((size_t)t * Bb + gro) * Oo + d] = o;
        }

        // rotate state buffers
        float* tmp;
        tmp = Wc; Wc = Wn; Wn = tmp;
        tmp = Ic; Ic = In; In = tmp;
        tmp = Ac; Ac = An; An = tmp;
    }
    #undef WL
}

extern "C" void kernel_launch(void* const* d_in, const int* in_sizes, int n_in,
                              void* d_out, int out_size) {
    const float* const* in = (const float* const*)d_in;
    const float *obs, *enc_w, *enc_b;
    const float *wW, *wI, *wA, *zW, *zI, *zA, *rW, *rIm, *rA, *hW, *hI, *hA, *aW, *aI, *aA;
    const float *att_w, *att_b, *wmg_w, *wmg_b, *img_w, *img_b, *amg_w, *amg_b;
    const float *z_b, *r_b, *h_b, *a_b, *phi_w, *phi_b;

    if (in_sizes[6] == 2048) {
        obs = in[0]; enc_w = in[1]; enc_b = in[2];
        wW = in[3]; wI = in[4]; wA = in[5];
        att_w = in[6]; att_b = in[7]; wmg_w = in[8]; wmg_b = in[9];
        zW = in[10]; zI = in[11]; zA = in[12]; z_b = in[13];
        rW = in[14]; rIm = in[15]; rA = in[16]; r_b = in[17];
        hW = in[18]; hI = in[19]; hA = in[20]; h_b = in[21];
        img_w = in[22]; img_b = in[23];
        aW = in[24]; aI = in[25]; aA = in[26]; a_b = in[27];
        amg_w = in[28]; amg_b = in[29];
        phi_w = in[30]; phi_b = in[31];
    } else {
        obs = in[0]; enc_w = in[1]; enc_b = in[2];
        wW = in[3]; wI = in[4]; wA = in[5];
        zW = in[6]; zI = in[7]; zA = in[8];
        rW = in[9]; rIm = in[10]; rA = in[11];
        hW = in[12]; hI = in[13]; hA = in[14];
        aW = in[15]; aI = in[16]; aA = in[17];
        att_w = in[18]; att_b = in[19];
        wmg_w = in[20]; wmg_b = in[21];
        img_w = in[22]; img_b = in[23];
        amg_w = in[24]; amg_b = in[25];
        z_b = in[26]; r_b = in[27]; h_b = in[28]; a_b = in[29];
        phi_w = in[30]; phi_b = in[31];
    }

    Params p;
    p.obs = obs; p.enc_w = enc_w;
    const float* sq[NMAT] = {
        wW, wI, wA,
        att_w, att_w + 32,
        wmg_w, wmg_w + 32,
        zW, zI, zA,
        rW, rIm, rA,
        hW, hI, hA,
        img_w, img_w + 32,
        aW, aI, aA,
        amg_w, amg_w + 32
    };
    const int rs[NMAT] = {
        32, 32, 32,
        64, 64,
        64, 64,
        32, 32, 32,
        32, 32, 32,
        32, 32, 32,
        64, 64,
        32, 32, 32,
        64, 64
    };
    for (int i = 0; i < NMAT; i++) { p.sq[i] = sq[i]; p.rs[i] = rs[i]; }
    const float* bv[9] = { att_b, wmg_b, img_b, amg_b, z_b, r_b, h_b, a_b, enc_b };
    for (int i = 0; i < 9; i++) p.bv[i] = bv[i];
    p.phi_w = phi_w; p.phi_b = phi_b;
    p.out = (float*)d_out;

    const int smemBytes = SM_TOT * (int)sizeof(float);
    cudaFuncSetAttribute(anima_kernel,
                         cudaFuncAttributeMaxDynamicSharedMemorySize, smemBytes);
    anima_kernel<<<Bb / ROWS, NTHR, smemBytes>>>(p);
}

// round 12
// speedup vs baseline: 1.0871x; 1.0124x over previous
#include <cuda_runtime.h>
#include <cstddef>

// Problem constants
#define Dd   32
#define Ss   8
#define Oo   4
#define Tt   256
#define Bb   1024
#define ROWS 8            // batch rows per CTA -> 128 CTAs (one per SM, single wave)
#define NTHR 256          // TWO independent groups of 128 threads:
                          //   group g (tid>>7) owns rows 4g..4g+3, synced by bar.sync g+1,128
                          // within group: t=tid&127, d=t>>2, s=(t>>1)&1, h=t&1
                          //   thread matvecs rows {4g+s, 4g+s+2}, owns (finalizes) row 4g+s+2h
#define ST   36           // padded row stride (floats) -> conflict-free smem
#define MS   (32*ST)      // floats per 32x32 matrix (padded)
#define RS   (ROWS*ST)    // floats per state buffer
#define NMAT 23

// smem float offsets
#define SM_ENC  (NMAT*MS)
#define SM_PHI  (SM_ENC + 32*8)
#define SM_BIAS (SM_PHI + 4*ST)
#define SM_ST   (SM_BIAS + 292)
#define SM_RI   (SM_ST + 6*RS)
#define SM_TOT  (SM_RI + RS)

// matrix slot order in smem:
// 0 wW 1 wI 2 wA | 3 att1 4 att2 | 5 wmg1 6 wmg2 | 7 zW 8 zI 9 zA |
// 10 rW 11 rIm 12 rA | 13 hW 14 hI 15 hA | 16 img1 17 img2 |
// 18 aW 19 aI 20 aA | 21 amg1 22 amg2

typedef unsigned long long u64;

struct Params {
    const float* obs;
    const float* enc_w;
    const float* sq[NMAT];
    int          rs[NMAT];
    const float* bv[9];
    const float* phi_w;
    const float* phi_b;
    float*       out;
};

__device__ __forceinline__ u64 f2fma(u64 a, u64 b, u64 c) {
    u64 d;
    asm("fma.rn.f32x2 %0, %1, %2, %3;" : "=l"(d) : "l"(a), "l"(b), "l"(c));
    return d;
}
__device__ __forceinline__ u64 f2add(u64 a, u64 b) {
    u64 d;
    asm("add.rn.f32x2 %0, %1, %2;" : "=l"(d) : "l"(a), "l"(b));
    return d;
}
__device__ __forceinline__ float psum(u64 a) {
    float lo = __uint_as_float((unsigned)(a & 0xffffffffull));
    float hi = __uint_as_float((unsigned)(a >> 32));
    return lo + hi;
}
// Exchange-reduce: keep own-row partial, swap other-row partial with h-partner (lane^1).
// mask must name exactly the converged lanes executing this call.
__device__ __forceinline__ float redu2(u64 x0, u64 x1, int h, float bias, unsigned mask) {
    float s0 = psum(x0);
    float s1 = psum(x1);
    float send = h ? s0 : s1;
    float own  = h ? s1 : s0;
    float recv = __shfl_xor_sync(mask, send, 1);
    return own + recv + bias;
}
// HW tanh (sm_75+ MUFU): 1 instruction, lat ~16
__device__ __forceinline__ float tanh_f(float x) {
    float y;
    asm("tanh.approx.f32 %0, %1;" : "=f"(y) : "f"(x));
    return y;
}
// sigmoid via HW tanh: sigm(x) = 0.5*tanh(x/2) + 0.5
__device__ __forceinline__ float sigm(float x) {
    return fmaf(tanh_f(0.5f * x), 0.5f, 0.5f);
}
__device__ __forceinline__ ulonglong2 ld2(const float* p) {
    return *(const ulonglong2*)p;
}
__device__ __forceinline__ void gsync(int bar) {
    asm volatile("bar.sync %0, %1;" :: "r"(bar), "r"(128) : "memory");
}
#define ACC2(acc, w, v) do { acc = f2fma((w).x, (v).x, acc); acc = f2fma((w).y, (v).y, acc); } while (0)
#define FULLM 0xffffffffu

__global__ __launch_bounds__(NTHR, 1)
void anima_kernel(const Params p) {
    extern __shared__ float sm[];
    const int tid = threadIdx.x;

    // ---- cooperative weight load into padded smem (whole CTA) ----
    #pragma unroll 1
    for (int m = 0; m < NMAT; m++) {
        const float* src = p.sq[m];
        const int rstr = p.rs[m];
        float* dst = sm + m * MS;
        #pragma unroll 1
        for (int i = tid; i < 1024; i += NTHR)
            dst[(i >> 5) * ST + (i & 31)] = src[(i >> 5) * rstr + (i & 31)];
    }
    sm[SM_ENC + tid] = p.enc_w[tid];   // 32x8 compact
    if (tid < 128)
        sm[SM_PHI + (tid >> 5) * ST + (tid & 31)] = p.phi_w[tid];
    if (tid < 32) {
        #pragma unroll
        for (int j = 0; j < 9; j++)
            sm[SM_BIAS + j * 32 + tid] = p.bv[j][tid];
        if (tid < 4) sm[SM_BIAS + 288 + tid] = p.phi_b[tid];
    }
    #pragma unroll 1
    for (int i = tid; i < 7 * RS; i += NTHR)
        sm[SM_ST + i] = 0.f;
    __syncthreads();

    const int gid  = tid >> 7;             // barrier group 0/1 -> rows 4g..4g+3
    const int bar  = gid + 1;              // named barrier id
    const int t7   = tid & 127;
    const int d    = t7 >> 2;              // 0..31
    const int s    = (t7 >> 1) & 1;        // row sub-slot
    const int h    = t7 & 1;               // k-half; owns row (4g+s+2h)
    const int kb   = h * 16;
    const int rb0  = (4 * gid + s) * ST;
    const int rb1  = rb0 + 2 * ST;
    const int rbo  = h ? rb1 : rb0;        // owned row base
    const int row0 = blockIdx.x * ROWS;
    const long gro = row0 + 4 * gid + s + 2 * h;   // owned global row
    const float* wd = sm + d * ST + kb;

    float* Wc = sm + SM_ST;      float* Wn = Wc + RS;
    float* Ic = Wn + RS;         float* In = Ic + RS;
    float* Ac = In + RS;         float* An = Ac + RS;
    float* RI = sm + SM_RI;

    const float attb = sm[SM_BIAS +   0 + d];
    const float wmgb = sm[SM_BIAS +  32 + d];
    const float imgb = sm[SM_BIAS +  64 + d];
    const float amgb = sm[SM_BIAS +  96 + d];
    const float zb   = sm[SM_BIAS + 128 + d];
    const float rbi  = sm[SM_BIAS + 160 + d];
    const float hbi  = sm[SM_BIAS + 192 + d];
    const float abi  = sm[SM_BIAS + 224 + d];
    const float encb = sm[SM_BIAS + 256 + d];
    const float phib = (d < Oo) ? sm[SM_BIAS + 288 + d] : 0.f;

    const ulonglong2 encA = ld2(sm + SM_ENC + d * 8);
    const ulonglong2 encB = ld2(sm + SM_ENC + d * 8 + 4);

    #define WL(m, c) ld2(wd + (m) * MS + (c) * 4)

    // hI (matrix 14) weights cached in registers for all steps (constant)
    const ulonglong2 whi0 = WL(14, 0), whi1 = WL(14, 1),
                     whi2 = WL(14, 2), whi3 = WL(14, 3);

    u64 icache[2][8];   // old I, this k-half, rows {rb0, rb1}
    u64 acache[2][8];   // old A
    u64 wcache[2][8];   // W_new (cached phase2 -> phase4)

    #pragma unroll 1
    for (int t = 0; t < Tt; t++) {
        // obs: own row only
        const float* ob = p.obs + ((size_t)t * Bb + gro) * Ss;
        ulonglong2 oa = *(const ulonglong2*)(ob);
        ulonglong2 obv = *(const ulonglong2*)(ob + 4);

        // ---- phase 1: W_all, attn, wmg, obs_enc -> W_new ----
        u64 w_w0 = 0, w_i0 = 0, w_a0 = 0, w_w1 = 0, w_i1 = 0, w_a1 = 0;
        u64 at_w0 = 0, at_i0 = 0, at_w1 = 0, at_i1 = 0;
        u64 mg_i0 = 0, mg_a0 = 0, mg_i1 = 0, mg_a1 = 0;
        #pragma unroll
        for (int c = 0; c < 4; c++) {
            const int ko = kb + c * 4;
            ulonglong2 w0 = WL(0, c), w1 = WL(1, c), w2 = WL(2, c);
            ulonglong2 w3 = WL(3, c), w4 = WL(4, c), w5 = WL(5, c), w6 = WL(6, c);
            ulonglong2 Wv0 = ld2(Wc + rb0 + ko), Wv1 = ld2(Wc + rb1 + ko);
            ulonglong2 Iv0 = ld2(Ic + rb0 + ko), Iv1 = ld2(Ic + rb1 + ko);
            ulonglong2 Av0 = ld2(Ac + rb0 + ko), Av1 = ld2(Ac + rb1 + ko);
            icache[0][2*c] = Iv0.x; icache[0][2*c+1] = Iv0.y;
            icache[1][2*c] = Iv1.x; icache[1][2*c+1] = Iv1.y;
            acache[0][2*c] = Av0.x; acache[0][2*c+1] = Av0.y;
            acache[1][2*c] = Av1.x; acache[1][2*c+1] = Av1.y;
            ACC2(w_w0, w0, Wv0);   ACC2(w_w1, w0, Wv1);
            ACC2(w_i0, w1, Iv0);   ACC2(w_i1, w1, Iv1);
            ACC2(w_a0, w2, Av0);   ACC2(w_a1, w2, Av1);
            ACC2(at_w0, w3, Wv0);  ACC2(at_w1, w3, Wv1);
            ACC2(at_i0, w4, Iv0);  ACC2(at_i1, w4, Iv1);
            ACC2(mg_i0, w5, Iv0);  ACC2(mg_i1, w5, Iv1);
            ACC2(mg_a0, w6, Av0);  ACC2(mg_a1, w6, Av1);
        }
        float sW  = redu2(f2add(f2add(w_w0, w_i0), w_a0),
                          f2add(f2add(w_w1, w_i1), w_a1), h, 0.f, FULLM);
        float sAt = redu2(f2add(at_w0, at_i0), f2add(at_w1, at_i1), h, attb, FULLM);
        float sMg = redu2(f2add(mg_i0, mg_a0), f2add(mg_i1, mg_a1), h, wmgb, FULLM);
        u64 e = f2fma(encA.x, oa.x, 0ull);
        e = f2fma(encA.y, oa.y, e);
        u64 eb = f2fma(encB.x, obv.x, 0ull);
        eb = f2fma(encB.y, obv.y, eb);
        float oe = tanh_f(encb + psum(f2add(e, eb)));
        float wnew = tanh_f(oe * sigm(sAt) + sW * sigm(sMg));
        Wn[rbo + d] = wnew;
        // prefetch phase-2 c=0 weights across the barrier (constant data, no hazard)
        ulonglong2 q7 = WL(7, 0),  q8 = WL(8, 0),  q9 = WL(9, 0);
        ulonglong2 qa = WL(10, 0), qb = WL(11, 0), qc = WL(12, 0);
        ulonglong2 qe = WL(13, 0), qf = WL(15, 0);
        ulonglong2 qg = WL(16, 0), qh = WL(17, 0);
        gsync(bar);

        // ---- phase 2: z, r, h-partial, mult_I ----
        u64 z_w0 = 0, z_i0 = 0, z_a0 = 0, z_w1 = 0, z_i1 = 0, z_a1 = 0;
        u64 r_w0 = 0, r_i0 = 0, r_a0 = 0, r_w1 = 0, r_i1 = 0, r_a1 = 0;
        u64 h_w0 = 0, h_a0 = 0, h_w1 = 0, h_a1 = 0;
        u64 mi_w0 = 0, mi_a0 = 0, mi_w1 = 0, mi_a1 = 0;
        #pragma unroll
        for (int c = 0; c < 4; c++) {
            const int ko = kb + c * 4;
            ulonglong2 Wv0 = ld2(Wn + rb0 + ko), Wv1 = ld2(Wn + rb1 + ko);
            wcache[0][2*c] = Wv0.x; wcache[0][2*c+1] = Wv0.y;
            wcache[1][2*c] = Wv1.x; wcache[1][2*c+1] = Wv1.y;
            ulonglong2 w7 = (c == 0) ? q7 : WL(7, c);
            ulonglong2 w8 = (c == 0) ? q8 : WL(8, c);
            ulonglong2 w9 = (c == 0) ? q9 : WL(9, c);
            ulonglong2 wa = (c == 0) ? qa : WL(10, c);
            ulonglong2 wb = (c == 0) ? qb : WL(11, c);
            ulonglong2 wc = (c == 0) ? qc : WL(12, c);
            ulonglong2 we = (c == 0) ? qe : WL(13, c);
            ulonglong2 wf = (c == 0) ? qf : WL(15, c);
            ulonglong2 wg = (c == 0) ? qg : WL(16, c);
            ulonglong2 wh = (c == 0) ? qh : WL(17, c);
            ulonglong2 Iv0 = { icache[0][2*c], icache[0][2*c+1] };
            ulonglong2 Iv1 = { icache[1][2*c], icache[1][2*c+1] };
            ulonglong2 Av0 = { acache[0][2*c], acache[0][2*c+1] };
            ulonglong2 Av1 = { acache[1][2*c], acache[1][2*c+1] };
            ACC2(z_w0, w7, Wv0);   ACC2(z_w1, w7, Wv1);
            ACC2(z_i0, w8, Iv0);   ACC2(z_i1, w8, Iv1);
            ACC2(z_a0, w9, Av0);   ACC2(z_a1, w9, Av1);
            ACC2(r_w0, wa, Wv0);   ACC2(r_w1, wa, Wv1);
            ACC2(r_i0, wb, Iv0);   ACC2(r_i1, wb, Iv1);
            ACC2(r_a0, wc, Av0);   ACC2(r_a1, wc, Av1);
            ACC2(h_w0, we, Wv0);   ACC2(h_w1, we, Wv1);
            ACC2(h_a0, wf, Av0);   ACC2(h_a1, wf, Av1);
            ACC2(mi_w0, wg, Wv0);  ACC2(mi_w1, wg, Wv1);
            ACC2(mi_a0, wh, Av0);  ACC2(mi_a1, wh, Av1);
        }
        float z  = sigm(redu2(f2add(f2add(z_w0, z_i0), z_a0),
                              f2add(f2add(z_w1, z_i1), z_a1), h, zb, FULLM));
        float rg = sigm(redu2(f2add(f2add(r_w0, r_i0), r_a0),
                              f2add(f2add(r_w1, r_i1), r_a1), h, rbi, FULLM));
        float mi = sigm(redu2(f2add(mi_w0, mi_a0), f2add(mi_w1, mi_a1), h, imgb, FULLM));
        float Iold = Ic[rbo + d];              // own row only
        RI[rbo + d] = rg * Iold;
        u64 hacc0 = f2add(h_w0, h_a0);
        u64 hacc1 = f2add(h_w1, h_a1);
        gsync(bar);

        // ---- phase 3: h = tanh(hpart + hI*(r.I)); I_new ----
        u64 hr0 = 0, hr1 = 0;
        {
            ulonglong2 R0, R1;
            R0 = ld2(RI + rb0 + kb);      R1 = ld2(RI + rb1 + kb);
            ACC2(hr0, whi0, R0);          ACC2(hr1, whi0, R1);
            R0 = ld2(RI + rb0 + kb + 4);  R1 = ld2(RI + rb1 + kb + 4);
            ACC2(hr0, whi1, R0);          ACC2(hr1, whi1, R1);
            R0 = ld2(RI + rb0 + kb + 8);  R1 = ld2(RI + rb1 + kb + 8);
            ACC2(hr0, whi2, R0);          ACC2(hr1, whi2, R1);
            R0 = ld2(RI + rb0 + kb + 12); R1 = ld2(RI + rb1 + kb + 12);
            ACC2(hr0, whi3, R0);          ACC2(hr1, whi3, R1);
        }
        float hv = tanh_f(redu2(f2add(hacc0, hr0), f2add(hacc1, hr1), h, hbi, FULLM));
        float inew = (1.f - z) * Iold + z * (hv * mi);
        In[rbo + d] = inew;
        // prefetch phase-4 c=0 weights across the barrier
        ulonglong2 qi = WL(18, 0), qj = WL(19, 0), qk = WL(20, 0);
        ulonglong2 ql = WL(21, 0), qm = WL(22, 0);
        gsync(bar);

        // ---- phase 4: A_all, mult_A -> A_new ----
        u64 a_w0 = 0, a_i0 = 0, a_a0 = 0, a_w1 = 0, a_i1 = 0, a_a1 = 0;
        u64 ma_w0 = 0, ma_i0 = 0, ma_w1 = 0, ma_i1 = 0;
        #pragma unroll
        for (int c = 0; c < 4; c++) {
            const int ko = kb + c * 4;
            ulonglong2 Wv0 = { wcache[0][2*c], wcache[0][2*c+1] };
            ulonglong2 Wv1 = { wcache[1][2*c], wcache[1][2*c+1] };
            ulonglong2 Nv0 = ld2(In + rb0 + ko), Nv1 = ld2(In + rb1 + ko);
            ulonglong2 Av0 = { acache[0][2*c], acache[0][2*c+1] };
            ulonglong2 Av1 = { acache[1][2*c], acache[1][2*c+1] };
            ulonglong2 wi = (c == 0) ? qi : WL(18, c);
            ulonglong2 wj = (c == 0) ? qj : WL(19, c);
            ulonglong2 wk = (c == 0) ? qk : WL(20, c);
            ulonglong2 wl = (c == 0) ? ql : WL(21, c);
            ulonglong2 wm = (c == 0) ? qm : WL(22, c);
            ACC2(a_w0, wi, Wv0);   ACC2(a_w1, wi, Wv1);
            ACC2(a_i0, wj, Nv0);   ACC2(a_i1, wj, Nv1);
            ACC2(a_a0, wk, Av0);   ACC2(a_a1, wk, Av1);
            ACC2(ma_w0, wl, Wv0);  ACC2(ma_w1, wl, Wv1);
            ACC2(ma_i0, wm, Nv0);  ACC2(ma_i1, wm, Nv1);
        }
        float sA  = redu2(f2add(f2add(a_w0, a_i0), a_a0),
                          f2add(f2add(a_w1, a_i1), a_a1), h, abi, FULLM);
        float sMa = redu2(f2add(ma_w0, ma_i0), f2add(ma_w1, ma_i1), h, amgb, FULLM);
        float anew = tanh_f(sA * sigm(sMa));
        An[rbo + d] = anew;
        gsync(bar);

        // ---- output: actions = phi(A_new); d<4 -> lanes 0..15 of warp 0 of each
        //      group: PARTIAL-WARP branch, so the shfl mask is 0xffff ----
        if (d < Oo) {
            u64 aO0 = 0, aO1 = 0;
            #pragma unroll
            for (int c = 0; c < 4; c++) {
                const int ko = kb + c * 4;
                ulonglong2 pw = ld2(sm + SM_PHI + d * ST + ko);
                ulonglong2 A0 = ld2(An + rb0 + ko), A1 = ld2(An + rb1 + ko);
                ACC2(aO0, pw, A0);
                ACC2(aO1, pw, A1);
            }
            float o = redu2(aO0, aO1, h, phib, 0x0000ffffu);
            p.out[((size_t)t * Bb + gro) * Oo + d] = o;
        }

        // rotate state buffers
        float* tmp;
        tmp = Wc; Wc = Wn; Wn = tmp;
        tmp = Ic; Ic = In; In = tmp;
        tmp = Ac; Ac = An; An = tmp;
    }
    #undef WL
}

extern "C" void kernel_launch(void* const* d_in, const int* in_sizes, int n_in,
                              void* d_out, int out_size) {
    const float* const* in = (const float* const*)d_in;
    const float *obs, *enc_w, *enc_b;
    const float *wW, *wI, *wA, *zW, *zI, *zA, *rW, *rIm, *rA, *hW, *hI, *hA, *aW, *aI, *aA;
    const float *att_w, *att_b, *wmg_w, *wmg_b, *img_w, *img_b, *amg_w, *amg_b;
    const float *z_b, *r_b, *h_b, *a_b, *phi_w, *phi_b;

    if (in_sizes[6] == 2048) {
        obs = in[0]; enc_w = in[1]; enc_b = in[2];
        wW = in[3]; wI = in[4]; wA = in[5];
        att_w = in[6]; att_b = in[7]; wmg_w = in[8]; wmg_b = in[9];
        zW = in[10]; zI = in[11]; zA = in[12]; z_b = in[13];
        rW = in[14]; rIm = in[15]; rA = in[16]; r_b = in[17];
        hW = in[18]; hI = in[19]; hA = in[20]; h_b = in[21];
        img_w = in[22]; img_b = in[23];
        aW = in[24]; aI = in[25]; aA = in[26]; a_b = in[27];
        amg_w = in[28]; amg_b = in[29];
        phi_w = in[30]; phi_b = in[31];
    } else {
        obs = in[0]; enc_w = in[1]; enc_b = in[2];
        wW = in[3]; wI = in[4]; wA = in[5];
        zW = in[6]; zI = in[7]; zA = in[8];
        rW = in[9]; rIm = in[10]; rA = in[11];
        hW = in[12]; hI = in[13]; hA = in[14];
        aW = in[15]; aI = in[16]; aA = in[17];
        att_w = in[18]; att_b = in[19];
        wmg_w = in[20]; wmg_b = in[21];
        img_w = in[22]; img_b = in[23];
        amg_w = in[24]; amg_b = in[25];
        z_b = in[26]; r_b = in[27]; h_b = in[28]; a_b = in[29];
        phi_w = in[30]; phi_b = in[31];
    }

    Params p;
    p.obs = obs; p.enc_w = enc_w;
    const float* sq[NMAT] = {
        wW, wI, wA,
        att_w, att_w + 32,
        wmg_w, wmg_w + 32,
        zW, zI, zA,
        rW, rIm, rA,
        hW, hI, hA,
        img_w, img_w + 32,
        aW, aI, aA,
        amg_w, amg_w + 32
    };
    const int rs[NMAT] = {
        32, 32, 32,
        64, 64,
        64, 64,
        32, 32, 32,
        32, 32, 32,
        32, 32, 32,
        64, 64,
        32, 32, 32,
        64, 64
    };
    for (int i = 0; i < NMAT; i++) { p.sq[i] = sq[i]; p.rs[i] = rs[i]; }
    const float* bv[9] = { att_b, wmg_b, img_b, amg_b, z_b, r_b, h_b, a_b, enc_b };
    for (int i = 0; i < 9; i++) p.bv[i] = bv[i];
    p.phi_w = phi_w; p.phi_b = phi_b;
    p.out = (float*)d_out;

    const int smemBytes = SM_TOT * (int)sizeof(float);
    cudaFuncSetAttribute(anima_kernel,
                         cudaFuncAttributeMaxDynamicSharedMemorySize, smemBytes);
    anima_kernel<<<Bb / ROWS, NTHR, smemBytes>>>(p);
}

// round 13
// speedup vs baseline: 1.1232x; 1.0332x over previous
#include <cuda_runtime.h>
#include <cstddef>

// Problem constants
#define Dd   32
#define Ss   8
#define Oo   4
#define Tt   256
#define Bb   1024
#define ROWS 8            // batch rows per CTA -> 128 CTAs (one per SM, single wave)
#define NTHR 256          // TWO independent groups of 128 threads:
                          //   group g (tid>>7) owns rows 4g..4g+3, synced by bar.sync g+1,128
                          // within group: t=tid&127, d=t>>2, s=(t>>1)&1, h=t&1
                          //   thread matvecs rows {4g+s, 4g+s+2}, owns (finalizes) row 4g+s+2h
#define ST   36           // padded row stride (floats) -> conflict-free smem
#define MS   (32*ST)      // floats per 32x32 matrix (padded)
#define RS   (ROWS*ST)    // floats per state buffer
#define NMAT 23

// smem float offsets
#define SM_ENC  (NMAT*MS)
#define SM_PHI  (SM_ENC + 32*8)
#define SM_BIAS (SM_PHI + 4*ST)
#define SM_ST   (SM_BIAS + 292)
#define SM_RI   (SM_ST + 6*RS)
#define SM_TOT  (SM_RI + RS)

// matrix slot order in smem:
// 0 wW 1 wI 2 wA | 3 att1 4 att2 | 5 wmg1 6 wmg2 | 7 zW 8 zI 9 zA |
// 10 rW 11 rIm 12 rA | 13 hW 14 hI 15 hA | 16 img1 17 img2 |
// 18 aW 19 aI 20 aA | 21 amg1 22 amg2

typedef unsigned long long u64;

struct Params {
    const float* obs;
    const float* enc_w;
    const float* sq[NMAT];
    int          rs[NMAT];
    const float* bv[9];
    const float* phi_w;
    const float* phi_b;
    float*       out;
};

__device__ __forceinline__ u64 f2fma(u64 a, u64 b, u64 c) {
    u64 d;
    asm("fma.rn.f32x2 %0, %1, %2, %3;" : "=l"(d) : "l"(a), "l"(b), "l"(c));
    return d;
}
__device__ __forceinline__ u64 f2add(u64 a, u64 b) {
    u64 d;
    asm("add.rn.f32x2 %0, %1, %2;" : "=l"(d) : "l"(a), "l"(b));
    return d;
}
__device__ __forceinline__ float psum(u64 a) {
    float lo = __uint_as_float((unsigned)(a & 0xffffffffull));
    float hi = __uint_as_float((unsigned)(a >> 32));
    return lo + hi;
}
// Exchange-reduce: keep own-row partial, swap other-row partial with h-partner (lane^1).
// mask must name exactly the converged lanes executing this call.
__device__ __forceinline__ float redu2(u64 x0, u64 x1, int h, float bias, unsigned mask) {
    float s0 = psum(x0);
    float s1 = psum(x1);
    float send = h ? s0 : s1;
    float own  = h ? s1 : s0;
    float recv = __shfl_xor_sync(mask, send, 1);
    return own + recv + bias;
}
// HW tanh (sm_75+ MUFU): 1 instruction, lat ~16
__device__ __forceinline__ float tanh_f(float x) {
    float y;
    asm("tanh.approx.f32 %0, %1;" : "=f"(y) : "f"(x));
    return y;
}
// sigmoid via HW tanh: sigm(x) = 0.5*tanh(x/2) + 0.5
__device__ __forceinline__ float sigm(float x) {
    return fmaf(tanh_f(0.5f * x), 0.5f, 0.5f);
}
__device__ __forceinline__ ulonglong2 ld2(const float* p) {
    return *(const ulonglong2*)p;
}
__device__ __forceinline__ void gsync(int bar) {
    asm volatile("bar.sync %0, %1;" :: "r"(bar), "r"(128) : "memory");
}
#define ACC2(acc, w, v) do { acc = f2fma((w).x, (v).x, acc); acc = f2fma((w).y, (v).y, acc); } while (0)
#define FULLM 0xffffffffu

__global__ __launch_bounds__(NTHR, 1)
void anima_kernel(const Params p) {
    extern __shared__ float sm[];
    const int tid = threadIdx.x;

    // ---- cooperative weight load into padded smem (whole CTA) ----
    #pragma unroll 1
    for (int m = 0; m < NMAT; m++) {
        const float* src = p.sq[m];
        const int rstr = p.rs[m];
        float* dst = sm + m * MS;
        #pragma unroll 1
        for (int i = tid; i < 1024; i += NTHR)
            dst[(i >> 5) * ST + (i & 31)] = src[(i >> 5) * rstr + (i & 31)];
    }
    sm[SM_ENC + tid] = p.enc_w[tid];   // 32x8 compact
    if (tid < 128)
        sm[SM_PHI + (tid >> 5) * ST + (tid & 31)] = p.phi_w[tid];
    if (tid < 32) {
        #pragma unroll
        for (int j = 0; j < 9; j++)
            sm[SM_BIAS + j * 32 + tid] = p.bv[j][tid];
        if (tid < 4) sm[SM_BIAS + 288 + tid] = p.phi_b[tid];
    }
    #pragma unroll 1
    for (int i = tid; i < 7 * RS; i += NTHR)
        sm[SM_ST + i] = 0.f;
    __syncthreads();

    const int gid  = tid >> 7;             // barrier group 0/1 -> rows 4g..4g+3
    const int bar  = gid + 1;              // named barrier id
    const int t7   = tid & 127;
    const int d    = t7 >> 2;              // 0..31
    const int s    = (t7 >> 1) & 1;        // row sub-slot
    const int h    = t7 & 1;               // k-half; owns row (4g+s+2h)
    const int kb   = h * 16;
    const int rb0  = (4 * gid + s) * ST;
    const int rb1  = rb0 + 2 * ST;
    const int rbo  = h ? rb1 : rb0;        // owned row base
    const int row0 = blockIdx.x * ROWS;
    const long gro = row0 + 4 * gid + s + 2 * h;   // owned global row
    const float* wd = sm + d * ST + kb;

    float* Wc = sm + SM_ST;      float* Wn = Wc + RS;
    float* Ic = Wn + RS;         float* In = Ic + RS;
    float* Ac = In + RS;         float* An = Ac + RS;
    float* RI = sm + SM_RI;

    const float attb = sm[SM_BIAS +   0 + d];
    const float wmgb = sm[SM_BIAS +  32 + d];
    const float imgb = sm[SM_BIAS +  64 + d];
    const float amgb = sm[SM_BIAS +  96 + d];
    const float zb   = sm[SM_BIAS + 128 + d];
    const float rbi  = sm[SM_BIAS + 160 + d];
    const float hbi  = sm[SM_BIAS + 192 + d];
    const float abi  = sm[SM_BIAS + 224 + d];
    const float encb = sm[SM_BIAS + 256 + d];
    const float phib = (d < Oo) ? sm[SM_BIAS + 288 + d] : 0.f;

    const ulonglong2 encA = ld2(sm + SM_ENC + d * 8);
    const ulonglong2 encB = ld2(sm + SM_ENC + d * 8 + 4);

    #define WL(m, c) ld2(wd + (m) * MS + (c) * 4)

    // Register-resident weights (constant over all 256 steps):
    // hI (m14, used in phase 3), aI (m19) and amg2 (m22, both multiplied by In
    // in phase 4's post-barrier critical path).
    const ulonglong2 whi0 = WL(14, 0), whi1 = WL(14, 1),
                     whi2 = WL(14, 2), whi3 = WL(14, 3);
    const ulonglong2 w19_0 = WL(19, 0), w19_1 = WL(19, 1),
                     w19_2 = WL(19, 2), w19_3 = WL(19, 3);
    const ulonglong2 w22_0 = WL(22, 0), w22_1 = WL(22, 1),
                     w22_2 = WL(22, 2), w22_3 = WL(22, 3);

    u64 icache[2][8];   // old I, this k-half, rows {rb0, rb1}
    u64 acache[2][8];   // old A
    u64 wcache[2][8];   // W_new (cached phase2 -> phase4)

    #pragma unroll 1
    for (int t = 0; t < Tt; t++) {
        // obs: own row only
        const float* ob = p.obs + ((size_t)t * Bb + gro) * Ss;
        ulonglong2 oa = *(const ulonglong2*)(ob);
        ulonglong2 obv = *(const ulonglong2*)(ob + 4);

        // ---- phase 1: W_all, attn, wmg, obs_enc -> W_new ----
        u64 w_w0 = 0, w_i0 = 0, w_a0 = 0, w_w1 = 0, w_i1 = 0, w_a1 = 0;
        u64 at_w0 = 0, at_i0 = 0, at_w1 = 0, at_i1 = 0;
        u64 mg_i0 = 0, mg_a0 = 0, mg_i1 = 0, mg_a1 = 0;
        #pragma unroll
        for (int c = 0; c < 4; c++) {
            const int ko = kb + c * 4;
            ulonglong2 w0 = WL(0, c), w1 = WL(1, c), w2 = WL(2, c);
            ulonglong2 w3 = WL(3, c), w4 = WL(4, c), w5 = WL(5, c), w6 = WL(6, c);
            ulonglong2 Wv0 = ld2(Wc + rb0 + ko), Wv1 = ld2(Wc + rb1 + ko);
            ulonglong2 Iv0 = ld2(Ic + rb0 + ko), Iv1 = ld2(Ic + rb1 + ko);
            ulonglong2 Av0 = ld2(Ac + rb0 + ko), Av1 = ld2(Ac + rb1 + ko);
            icache[0][2*c] = Iv0.x; icache[0][2*c+1] = Iv0.y;
            icache[1][2*c] = Iv1.x; icache[1][2*c+1] = Iv1.y;
            acache[0][2*c] = Av0.x; acache[0][2*c+1] = Av0.y;
            acache[1][2*c] = Av1.x; acache[1][2*c+1] = Av1.y;
            ACC2(w_w0, w0, Wv0);   ACC2(w_w1, w0, Wv1);
            ACC2(w_i0, w1, Iv0);   ACC2(w_i1, w1, Iv1);
            ACC2(w_a0, w2, Av0);   ACC2(w_a1, w2, Av1);
            ACC2(at_w0, w3, Wv0);  ACC2(at_w1, w3, Wv1);
            ACC2(at_i0, w4, Iv0);  ACC2(at_i1, w4, Iv1);
            ACC2(mg_i0, w5, Iv0);  ACC2(mg_i1, w5, Iv1);
            ACC2(mg_a0, w6, Av0);  ACC2(mg_a1, w6, Av1);
        }
        float sW  = redu2(f2add(f2add(w_w0, w_i0), w_a0),
                          f2add(f2add(w_w1, w_i1), w_a1), h, 0.f, FULLM);
        float sAt = redu2(f2add(at_w0, at_i0), f2add(at_w1, at_i1), h, attb, FULLM);
        float sMg = redu2(f2add(mg_i0, mg_a0), f2add(mg_i1, mg_a1), h, wmgb, FULLM);
        u64 e = f2fma(encA.x, oa.x, 0ull);
        e = f2fma(encA.y, oa.y, e);
        u64 eb = f2fma(encB.x, obv.x, 0ull);
        eb = f2fma(encB.y, obv.y, eb);
        float oe = tanh_f(encb + psum(f2add(e, eb)));
        float wnew = tanh_f(oe * sigm(sAt) + sW * sigm(sMg));
        Wn[rbo + d] = wnew;
        // prefetch phase-2 c=0 weights across the barrier (constant data, no hazard)
        ulonglong2 q7 = WL(7, 0),  q8 = WL(8, 0),  q9 = WL(9, 0);
        ulonglong2 qa = WL(10, 0), qb = WL(11, 0), qc = WL(12, 0);
        ulonglong2 qe = WL(13, 0), qf = WL(15, 0);
        ulonglong2 qg = WL(16, 0), qh = WL(17, 0);
        gsync(bar);

        // ---- phase 2: z, r, h-partial, mult_I ----
        u64 z_w0 = 0, z_i0 = 0, z_a0 = 0, z_w1 = 0, z_i1 = 0, z_a1 = 0;
        u64 r_w0 = 0, r_i0 = 0, r_a0 = 0, r_w1 = 0, r_i1 = 0, r_a1 = 0;
        u64 h_w0 = 0, h_a0 = 0, h_w1 = 0, h_a1 = 0;
        u64 mi_w0 = 0, mi_a0 = 0, mi_w1 = 0, mi_a1 = 0;
        #pragma unroll
        for (int c = 0; c < 4; c++) {
            const int ko = kb + c * 4;
            ulonglong2 Wv0 = ld2(Wn + rb0 + ko), Wv1 = ld2(Wn + rb1 + ko);
            wcache[0][2*c] = Wv0.x; wcache[0][2*c+1] = Wv0.y;
            wcache[1][2*c] = Wv1.x; wcache[1][2*c+1] = Wv1.y;
            ulonglong2 w7 = (c == 0) ? q7 : WL(7, c);
            ulonglong2 w8 = (c == 0) ? q8 : WL(8, c);
            ulonglong2 w9 = (c == 0) ? q9 : WL(9, c);
            ulonglong2 wa = (c == 0) ? qa : WL(10, c);
            ulonglong2 wb = (c == 0) ? qb : WL(11, c);
            ulonglong2 wc = (c == 0) ? qc : WL(12, c);
            ulonglong2 we = (c == 0) ? qe : WL(13, c);
            ulonglong2 wf = (c == 0) ? qf : WL(15, c);
            ulonglong2 wg = (c == 0) ? qg : WL(16, c);
            ulonglong2 wh = (c == 0) ? qh : WL(17, c);
            ulonglong2 Iv0 = { icache[0][2*c], icache[0][2*c+1] };
            ulonglong2 Iv1 = { icache[1][2*c], icache[1][2*c+1] };
            ulonglong2 Av0 = { acache[0][2*c], acache[0][2*c+1] };
            ulonglong2 Av1 = { acache[1][2*c], acache[1][2*c+1] };
            ACC2(z_w0, w7, Wv0);   ACC2(z_w1, w7, Wv1);
            ACC2(z_i0, w8, Iv0);   ACC2(z_i1, w8, Iv1);
            ACC2(z_a0, w9, Av0);   ACC2(z_a1, w9, Av1);
            ACC2(r_w0, wa, Wv0);   ACC2(r_w1, wa, Wv1);
            ACC2(r_i0, wb, Iv0);   ACC2(r_i1, wb, Iv1);
            ACC2(r_a0, wc, Av0);   ACC2(r_a1, wc, Av1);
            ACC2(h_w0, we, Wv0);   ACC2(h_w1, we, Wv1);
            ACC2(h_a0, wf, Av0);   ACC2(h_a1, wf, Av1);
            ACC2(mi_w0, wg, Wv0);  ACC2(mi_w1, wg, Wv1);
            ACC2(mi_a0, wh, Av0);  ACC2(mi_a1, wh, Av1);
        }
        float z  = sigm(redu2(f2add(f2add(z_w0, z_i0), z_a0),
                              f2add(f2add(z_w1, z_i1), z_a1), h, zb, FULLM));
        float rg = sigm(redu2(f2add(f2add(r_w0, r_i0), r_a0),
                              f2add(f2add(r_w1, r_i1), r_a1), h, rbi, FULLM));
        float mi = sigm(redu2(f2add(mi_w0, mi_a0), f2add(mi_w1, mi_a1), h, imgb, FULLM));
        float Iold = Ic[rbo + d];              // own row only
        RI[rbo + d] = rg * Iold;
        u64 hacc0 = f2add(h_w0, h_a0);
        u64 hacc1 = f2add(h_w1, h_a1);
        gsync(bar);

        // ---- phase 3: h = tanh(hpart + hI*(r.I)); I_new ----
        u64 hr0 = 0, hr1 = 0;
        {
            ulonglong2 R0, R1;
            R0 = ld2(RI + rb0 + kb);      R1 = ld2(RI + rb1 + kb);
            ACC2(hr0, whi0, R0);          ACC2(hr1, whi0, R1);
            R0 = ld2(RI + rb0 + kb + 4);  R1 = ld2(RI + rb1 + kb + 4);
            ACC2(hr0, whi1, R0);          ACC2(hr1, whi1, R1);
            R0 = ld2(RI + rb0 + kb + 8);  R1 = ld2(RI + rb1 + kb + 8);
            ACC2(hr0, whi2, R0);          ACC2(hr1, whi2, R1);
            R0 = ld2(RI + rb0 + kb + 12); R1 = ld2(RI + rb1 + kb + 12);
            ACC2(hr0, whi3, R0);          ACC2(hr1, whi3, R1);
        }
        float hv = tanh_f(redu2(f2add(hacc0, hr0), f2add(hacc1, hr1), h, hbi, FULLM));
        float inew = (1.f - z) * Iold + z * (hv * mi);
        In[rbo + d] = inew;
        // prefetch phase-4 c=0 weights across the barrier (m19/m22 now in regs)
        ulonglong2 qi = WL(18, 0), qk = WL(20, 0), ql = WL(21, 0);
        gsync(bar);

        // ---- phase 4: A_all, mult_A -> A_new ----
        u64 a_w0 = 0, a_i0 = 0, a_a0 = 0, a_w1 = 0, a_i1 = 0, a_a1 = 0;
        u64 ma_w0 = 0, ma_i0 = 0, ma_w1 = 0, ma_i1 = 0;
        #pragma unroll
        for (int c = 0; c < 4; c++) {
            const int ko = kb + c * 4;
            ulonglong2 Wv0 = { wcache[0][2*c], wcache[0][2*c+1] };
            ulonglong2 Wv1 = { wcache[1][2*c], wcache[1][2*c+1] };
            ulonglong2 Nv0 = ld2(In + rb0 + ko), Nv1 = ld2(In + rb1 + ko);
            ulonglong2 Av0 = { acache[0][2*c], acache[0][2*c+1] };
            ulonglong2 Av1 = { acache[1][2*c], acache[1][2*c+1] };
            ulonglong2 wi = (c == 0) ? qi : WL(18, c);
            ulonglong2 wk = (c == 0) ? qk : WL(20, c);
            ulonglong2 wl = (c == 0) ? ql : WL(21, c);
            ulonglong2 wj = (c == 0) ? w19_0 : (c == 1) ? w19_1 : (c == 2) ? w19_2 : w19_3;
            ulonglong2 wm = (c == 0) ? w22_0 : (c == 1) ? w22_1 : (c == 2) ? w22_2 : w22_3;
            ACC2(a_w0, wi, Wv0);   ACC2(a_w1, wi, Wv1);
            ACC2(a_i0, wj, Nv0);   ACC2(a_i1, wj, Nv1);
            ACC2(a_a0, wk, Av0);   ACC2(a_a1, wk, Av1);
            ACC2(ma_w0, wl, Wv0);  ACC2(ma_w1, wl, Wv1);
            ACC2(ma_i0, wm, Nv0);  ACC2(ma_i1, wm, Nv1);
        }
        float sA  = redu2(f2add(f2add(a_w0, a_i0), a_a0),
                          f2add(f2add(a_w1, a_i1), a_a1), h, abi, FULLM);
        float sMa = redu2(f2add(ma_w0, ma_i0), f2add(ma_w1, ma_i1), h, amgb, FULLM);
        float anew = tanh_f(sA * sigm(sMa));
        An[rbo + d] = anew;
        gsync(bar);

        // ---- output: actions = phi(A_new); d<4 -> lanes 0..15 of warp 0 of each
        //      group: PARTIAL-WARP branch, so the shfl mask is 0xffff ----
        if (d < Oo) {
            u64 aO0 = 0, aO1 = 0;
            #pragma unroll
            for (int c = 0; c < 4; c++) {
                const int ko = kb + c * 4;
                ulonglong2 pw = ld2(sm + SM_PHI + d * ST + ko);
                ulonglong2 A0 = ld2(An + rb0 + ko), A1 = ld2(An + rb1 + ko);
                ACC2(aO0, pw, A0);
                ACC2(aO1, pw, A1);
            }
            float o = redu2(aO0, aO1, h, phib, 0x0000ffffu);
            p.out[((size_t)t * Bb + gro) * Oo + d] = o;
        }

        // rotate state buffers
        float* tmp;
        tmp = Wc; Wc = Wn; Wn = tmp;
        tmp = Ic; Ic = In; In = tmp;
        tmp = Ac; Ac = An; An = tmp;
    }
    #undef WL
}

extern "C" void kernel_launch(void* const* d_in, const int* in_sizes, int n_in,
                              void* d_out, int out_size) {
    const float* const* in = (const float* const*)d_in;
    const float *obs, *enc_w, *enc_b;
    const float *wW, *wI, *wA, *zW, *zI, *zA, *rW, *rIm, *rA, *hW, *hI, *hA, *aW, *aI, *aA;
    const float *att_w, *att_b, *wmg_w, *wmg_b, *img_w, *img_b, *amg_w, *amg_b;
    const float *z_b, *r_b, *h_b, *a_b, *phi_w, *phi_b;

    if (in_sizes[6] == 2048) {
        obs = in[0]; enc_w = in[1]; enc_b = in[2];
        wW = in[3]; wI = in[4]; wA = in[5];
        att_w = in[6]; att_b = in[7]; wmg_w = in[8]; wmg_b = in[9];
        zW = in[10]; zI = in[11]; zA = in[12]; z_b = in[13];
        rW = in[14]; rIm = in[15]; rA = in[16]; r_b = in[17];
        hW = in[18]; hI = in[19]; hA = in[20]; h_b = in[21];
        img_w = in[22]; img_b = in[23];
        aW = in[24]; aI = in[25]; aA = in[26]; a_b = in[27];
        amg_w = in[28]; amg_b = in[29];
        phi_w = in[30]; phi_b = in[31];
    } else {
        obs = in[0]; enc_w = in[1]; enc_b = in[2];
        wW = in[3]; wI = in[4]; wA = in[5];
        zW = in[6]; zI = in[7]; zA = in[8];
        rW = in[9]; rIm = in[10]; rA = in[11];
        hW = in[12]; hI = in[13]; hA = in[14];
        aW = in[15]; aI = in[16]; aA = in[17];
        att_w = in[18]; att_b = in[19];
        wmg_w = in[20]; wmg_b = in[21];
        img_w = in[22]; img_b = in[23];
        amg_w = in[24]; amg_b = in[25];
        z_b = in[26]; r_b = in[27]; h_b = in[28]; a_b = in[29];
        phi_w = in[30]; phi_b = in[31];
    }

    Params p;
    p.obs = obs; p.enc_w = enc_w;
    const float* sq[NMAT] = {
        wW, wI, wA,
        att_w, att_w + 32,
        wmg_w, wmg_w + 32,
        zW, zI, zA,
        rW, rIm, rA,
        hW, hI, hA,
        img_w, img_w + 32,
        aW, aI, aA,
        amg_w, amg_w + 32
    };
    const int rs[NMAT] = {
        32, 32, 32,
        64, 64,
        64, 64,
        32, 32, 32,
        32, 32, 32,
        32, 32, 32,
        64, 64,
        32, 32, 32,
        64, 64
    };
    for (int i = 0; i < NMAT; i++) { p.sq[i] = sq[i]; p.rs[i] = rs[i]; }
    const float* bv[9] = { att_b, wmg_b, img_b, amg_b, z_b, r_b, h_b, a_b, enc_b };
    for (int i = 0; i < 9; i++) p.bv[i] = bv[i];
    p.phi_w = phi_w; p.phi_b = phi_b;
    p.out = (float*)d_out;

    const int smemBytes = SM_TOT * (int)sizeof(float);
    cudaFuncSetAttribute(anima_kernel,
                         cudaFuncAttributeMaxDynamicSharedMemorySize, smemBytes);
    anima_kernel<<<Bb / ROWS, NTHR, smemBytes>>>(p);
}

// round 14
// speedup vs baseline: 1.1684x; 1.0402x over previous
#include <cuda_runtime.h>
#include <cstddef>

// Problem constants
#define Dd   32
#define Ss   8
#define Oo   4
#define Tt   256
#define Bb   1024
#define ROWS 8            // batch rows per CTA -> 128 CTAs (one per SM, single wave)
#define NTHR 256          // TWO independent groups of 128 threads:
                          //   group g (tid>>7) owns rows 4g..4g+3, synced by bar.sync g+1,128
                          // within group: t=tid&127, d=t>>2, s=(t>>1)&1, h=t&1
                          //   thread matvecs rows {4g+s, 4g+s+2}, owns (finalizes) row 4g+s+2h
#define ST   36           // padded row stride (floats) -> conflict-free smem
#define MS   (32*ST)      // floats per 32x32 matrix (padded)
#define RS   (ROWS*ST)    // floats per state buffer
#define NMAT 23

// smem float offsets
#define SM_ENC  (NMAT*MS)
#define SM_PHI  (SM_ENC + 32*8)
#define SM_BIAS (SM_PHI + 4*ST)
#define SM_ST   (SM_BIAS + 292)
#define SM_RI   (SM_ST + 6*RS)
#define SM_TOT  (SM_RI + RS)

// matrix slot order in smem:
// 0 wW 1 wI 2 wA | 3 att1 4 att2 | 5 wmg1 6 wmg2 | 7 zW 8 zI 9 zA |
// 10 rW 11 rIm 12 rA | 13 hW 14 hI 15 hA | 16 img1 17 img2 |
// 18 aW 19 aI 20 aA | 21 amg1 22 amg2

typedef unsigned long long u64;

struct Params {
    const float* obs;
    const float* enc_w;
    const float* sq[NMAT];
    int          rs[NMAT];
    const float* bv[9];
    const float* phi_w;
    const float* phi_b;
    float*       out;
};

__device__ __forceinline__ u64 f2fma(u64 a, u64 b, u64 c) {
    u64 d;
    asm("fma.rn.f32x2 %0, %1, %2, %3;" : "=l"(d) : "l"(a), "l"(b), "l"(c));
    return d;
}
__device__ __forceinline__ u64 f2add(u64 a, u64 b) {
    u64 d;
    asm("add.rn.f32x2 %0, %1, %2;" : "=l"(d) : "l"(a), "l"(b));
    return d;
}
__device__ __forceinline__ float psum(u64 a) {
    float lo = __uint_as_float((unsigned)(a & 0xffffffffull));
    float hi = __uint_as_float((unsigned)(a >> 32));
    return lo + hi;
}
// Exchange-reduce: keep own-row partial, swap other-row partial with h-partner (lane^1).
// mask must name exactly the converged lanes executing this call.
__device__ __forceinline__ float redu2(u64 x0, u64 x1, int h, float bias, unsigned mask) {
    float s0 = psum(x0);
    float s1 = psum(x1);
    float send = h ? s0 : s1;
    float own  = h ? s1 : s0;
    float recv = __shfl_xor_sync(mask, send, 1);
    return own + recv + bias;
}
// HW tanh (sm_75+ MUFU): 1 instruction, lat ~16
__device__ __forceinline__ float tanh_f(float x) {
    float y;
    asm("tanh.approx.f32 %0, %1;" : "=f"(y) : "f"(x));
    return y;
}
// sigmoid via HW tanh: sigm(x) = 0.5*tanh(x/2) + 0.5
__device__ __forceinline__ float sigm(float x) {
    return fmaf(tanh_f(0.5f * x), 0.5f, 0.5f);
}
__device__ __forceinline__ ulonglong2 ld2(const float* p) {
    return *(const ulonglong2*)p;
}
__device__ __forceinline__ void gsync(int bar) {
    asm volatile("bar.sync %0, %1;" :: "r"(bar), "r"(128) : "memory");
}
#define ACC2(acc, w, v) do { acc = f2fma((w).x, (v).x, acc); acc = f2fma((w).y, (v).y, acc); } while (0)
#define FULLM 0xffffffffu

__global__ __launch_bounds__(NTHR, 1)
void anima_kernel(const Params p) {
    extern __shared__ float sm[];
    const int tid = threadIdx.x;

    // ---- cooperative weight load into padded smem (whole CTA) ----
    #pragma unroll 1
    for (int m = 0; m < NMAT; m++) {
        const float* src = p.sq[m];
        const int rstr = p.rs[m];
        float* dst = sm + m * MS;
        #pragma unroll 1
        for (int i = tid; i < 1024; i += NTHR)
            dst[(i >> 5) * ST + (i & 31)] = src[(i >> 5) * rstr + (i & 31)];
    }
    sm[SM_ENC + tid] = p.enc_w[tid];   // 32x8 compact
    if (tid < 128)
        sm[SM_PHI + (tid >> 5) * ST + (tid & 31)] = p.phi_w[tid];
    if (tid < 32) {
        #pragma unroll
        for (int j = 0; j < 9; j++)
            sm[SM_BIAS + j * 32 + tid] = p.bv[j][tid];
        if (tid < 4) sm[SM_BIAS + 288 + tid] = p.phi_b[tid];
    }
    #pragma unroll 1
    for (int i = tid; i < 7 * RS; i += NTHR)
        sm[SM_ST + i] = 0.f;
    __syncthreads();

    const int gid  = tid >> 7;             // barrier group 0/1 -> rows 4g..4g+3
    const int bar  = gid + 1;              // named barrier id
    const int t7   = tid & 127;
    const int d    = t7 >> 2;              // 0..31
    const int s    = (t7 >> 1) & 1;        // row sub-slot
    const int h    = t7 & 1;               // k-half; owns row (4g+s+2h)
    const int kb   = h * 16;
    const int rb0  = (4 * gid + s) * ST;
    const int rb1  = rb0 + 2 * ST;
    const int rbo  = h ? rb1 : rb0;        // owned row base
    const int row0 = blockIdx.x * ROWS;
    const long gro = row0 + 4 * gid + s + 2 * h;   // owned global row
    const float* wd = sm + d * ST + kb;

    float* Wc = sm + SM_ST;      float* Wn = Wc + RS;
    float* Ic = Wn + RS;         float* In = Ic + RS;
    float* Ac = In + RS;         float* An = Ac + RS;
    float* RI = sm + SM_RI;

    const float attb = sm[SM_BIAS +   0 + d];
    const float wmgb = sm[SM_BIAS +  32 + d];
    const float imgb = sm[SM_BIAS +  64 + d];
    const float amgb = sm[SM_BIAS +  96 + d];
    const float zb   = sm[SM_BIAS + 128 + d];
    const float rbi  = sm[SM_BIAS + 160 + d];
    const float hbi  = sm[SM_BIAS + 192 + d];
    const float abi  = sm[SM_BIAS + 224 + d];
    const float encb = sm[SM_BIAS + 256 + d];
    const float phib = (d < Oo) ? sm[SM_BIAS + 288 + d] : 0.f;

    const ulonglong2 encA = ld2(sm + SM_ENC + d * 8);
    const ulonglong2 encB = ld2(sm + SM_ENC + d * 8 + 4);

    #define WL(m, c) ld2(wd + (m) * MS + (c) * 4)

    // Register-resident weights (constant over all 256 steps):
    //   m14 hI   (phase-3 critical path)
    //   m19 aI, m22 amg2  (phase-4 In-chains)
    //   m7  zW,  m21 amg1 (phase-2 Wn-chains)
    const ulonglong2 whi0 = WL(14, 0), whi1 = WL(14, 1),
                     whi2 = WL(14, 2), whi3 = WL(14, 3);
    const ulonglong2 w19_0 = WL(19, 0), w19_1 = WL(19, 1),
                     w19_2 = WL(19, 2), w19_3 = WL(19, 3);
    const ulonglong2 w22_0 = WL(22, 0), w22_1 = WL(22, 1),
                     w22_2 = WL(22, 2), w22_3 = WL(22, 3);
    const ulonglong2 w7_0 = WL(7, 0), w7_1 = WL(7, 1),
                     w7_2 = WL(7, 2), w7_3 = WL(7, 3);
    const ulonglong2 w21_0 = WL(21, 0), w21_1 = WL(21, 1),
                     w21_2 = WL(21, 2), w21_3 = WL(21, 3);

    u64 icache[2][8];   // old I, this k-half, rows {rb0, rb1}
    u64 acache[2][8];   // old A

    #pragma unroll 1
    for (int t = 0; t < Tt; t++) {
        // obs: own row only
        const float* ob = p.obs + ((size_t)t * Bb + gro) * Ss;
        ulonglong2 oa = *(const ulonglong2*)(ob);
        ulonglong2 obv = *(const ulonglong2*)(ob + 4);

        // ---- phase 1: W_all, attn, wmg, obs_enc -> W_new ----
        u64 w_w0 = 0, w_i0 = 0, w_a0 = 0, w_w1 = 0, w_i1 = 0, w_a1 = 0;
        u64 at_w0 = 0, at_i0 = 0, at_w1 = 0, at_i1 = 0;
        u64 mg_i0 = 0, mg_a0 = 0, mg_i1 = 0, mg_a1 = 0;
        #pragma unroll
        for (int c = 0; c < 4; c++) {
            const int ko = kb + c * 4;
            ulonglong2 w0 = WL(0, c), w1 = WL(1, c), w2 = WL(2, c);
            ulonglong2 w3 = WL(3, c), w4 = WL(4, c), w5 = WL(5, c), w6 = WL(6, c);
            ulonglong2 Wv0 = ld2(Wc + rb0 + ko), Wv1 = ld2(Wc + rb1 + ko);
            ulonglong2 Iv0 = ld2(Ic + rb0 + ko), Iv1 = ld2(Ic + rb1 + ko);
            ulonglong2 Av0 = ld2(Ac + rb0 + ko), Av1 = ld2(Ac + rb1 + ko);
            icache[0][2*c] = Iv0.x; icache[0][2*c+1] = Iv0.y;
            icache[1][2*c] = Iv1.x; icache[1][2*c+1] = Iv1.y;
            acache[0][2*c] = Av0.x; acache[0][2*c+1] = Av0.y;
            acache[1][2*c] = Av1.x; acache[1][2*c+1] = Av1.y;
            ACC2(w_w0, w0, Wv0);   ACC2(w_w1, w0, Wv1);
            ACC2(w_i0, w1, Iv0);   ACC2(w_i1, w1, Iv1);
            ACC2(w_a0, w2, Av0);   ACC2(w_a1, w2, Av1);
            ACC2(at_w0, w3, Wv0);  ACC2(at_w1, w3, Wv1);
            ACC2(at_i0, w4, Iv0);  ACC2(at_i1, w4, Iv1);
            ACC2(mg_i0, w5, Iv0);  ACC2(mg_i1, w5, Iv1);
            ACC2(mg_a0, w6, Av0);  ACC2(mg_a1, w6, Av1);
        }
        float sW  = redu2(f2add(f2add(w_w0, w_i0), w_a0),
                          f2add(f2add(w_w1, w_i1), w_a1), h, 0.f, FULLM);
        float sAt = redu2(f2add(at_w0, at_i0), f2add(at_w1, at_i1), h, attb, FULLM);
        float sMg = redu2(f2add(mg_i0, mg_a0), f2add(mg_i1, mg_a1), h, wmgb, FULLM);
        u64 e = f2fma(encA.x, oa.x, 0ull);
        e = f2fma(encA.y, oa.y, e);
        u64 eb = f2fma(encB.x, obv.x, 0ull);
        eb = f2fma(encB.y, obv.y, eb);
        float oe = tanh_f(encb + psum(f2add(e, eb)));
        float wnew = tanh_f(oe * sigm(sAt) + sW * sigm(sMg));
        Wn[rbo + d] = wnew;
        // prefetch phase-2 c=0 weights across the barrier (m7/m21 now in regs)
        ulonglong2 q8 = WL(8, 0),  q9 = WL(9, 0);
        ulonglong2 qa = WL(10, 0), qb = WL(11, 0), qc = WL(12, 0);
        ulonglong2 qe = WL(13, 0), qf = WL(15, 0);
        ulonglong2 qg = WL(16, 0), qh = WL(17, 0);
        ulonglong2 qi = WL(18, 0);
        gsync(bar);

        // ---- phase 2: z, r, h-partial, mult_I + phase-4 Wn-chains (aW, amg1) ----
        u64 z_w0 = 0, z_i0 = 0, z_a0 = 0, z_w1 = 0, z_i1 = 0, z_a1 = 0;
        u64 r_w0 = 0, r_i0 = 0, r_a0 = 0, r_w1 = 0, r_i1 = 0, r_a1 = 0;
        u64 h_w0 = 0, h_a0 = 0, h_w1 = 0, h_a1 = 0;
        u64 mi_w0 = 0, mi_a0 = 0, mi_w1 = 0, mi_a1 = 0;
        u64 a_w0 = 0, a_w1 = 0, ma_w0 = 0, ma_w1 = 0;   // phase-4 precompute
        #pragma unroll
        for (int c = 0; c < 4; c++) {
            const int ko = kb + c * 4;
            ulonglong2 Wv0 = ld2(Wn + rb0 + ko), Wv1 = ld2(Wn + rb1 + ko);
            ulonglong2 w7 = (c == 0) ? w7_0 : (c == 1) ? w7_1 : (c == 2) ? w7_2 : w7_3;
            ulonglong2 wl = (c == 0) ? w21_0 : (c == 1) ? w21_1 : (c == 2) ? w21_2 : w21_3;
            ulonglong2 w8 = (c == 0) ? q8 : WL(8, c);
            ulonglong2 w9 = (c == 0) ? q9 : WL(9, c);
            ulonglong2 wa = (c == 0) ? qa : WL(10, c);
            ulonglong2 wb = (c == 0) ? qb : WL(11, c);
            ulonglong2 wc = (c == 0) ? qc : WL(12, c);
            ulonglong2 we = (c == 0) ? qe : WL(13, c);
            ulonglong2 wf = (c == 0) ? qf : WL(15, c);
            ulonglong2 wg = (c == 0) ? qg : WL(16, c);
            ulonglong2 wh = (c == 0) ? qh : WL(17, c);
            ulonglong2 wi = (c == 0) ? qi : WL(18, c);
            ulonglong2 Iv0 = { icache[0][2*c], icache[0][2*c+1] };
            ulonglong2 Iv1 = { icache[1][2*c], icache[1][2*c+1] };
            ulonglong2 Av0 = { acache[0][2*c], acache[0][2*c+1] };
            ulonglong2 Av1 = { acache[1][2*c], acache[1][2*c+1] };
            ACC2(z_w0, w7, Wv0);   ACC2(z_w1, w7, Wv1);
            ACC2(z_i0, w8, Iv0);   ACC2(z_i1, w8, Iv1);
            ACC2(z_a0, w9, Av0);   ACC2(z_a1, w9, Av1);
            ACC2(r_w0, wa, Wv0);   ACC2(r_w1, wa, Wv1);
            ACC2(r_i0, wb, Iv0);   ACC2(r_i1, wb, Iv1);
            ACC2(r_a0, wc, Av0);   ACC2(r_a1, wc, Av1);
            ACC2(h_w0, we, Wv0);   ACC2(h_w1, we, Wv1);
            ACC2(h_a0, wf, Av0);   ACC2(h_a1, wf, Av1);
            ACC2(mi_w0, wg, Wv0);  ACC2(mi_w1, wg, Wv1);
            ACC2(mi_a0, wh, Av0);  ACC2(mi_a1, wh, Av1);
            ACC2(a_w0, wi, Wv0);   ACC2(a_w1, wi, Wv1);
            ACC2(ma_w0, wl, Wv0);  ACC2(ma_w1, wl, Wv1);
        }
        float z  = sigm(redu2(f2add(f2add(z_w0, z_i0), z_a0),
                              f2add(f2add(z_w1, z_i1), z_a1), h, zb, FULLM));
        float rg = sigm(redu2(f2add(f2add(r_w0, r_i0), r_a0),
                              f2add(f2add(r_w1, r_i1), r_a1), h, rbi, FULLM));
        float mi = sigm(redu2(f2add(mi_w0, mi_a0), f2add(mi_w1, mi_a1), h, imgb, FULLM));
        float Iold = Ic[rbo + d];              // own row only
        RI[rbo + d] = rg * Iold;
        u64 hacc0 = f2add(h_w0, h_a0);
        u64 hacc1 = f2add(h_w1, h_a1);
        gsync(bar);

        // ---- phase 3: h = tanh(hpart + hI*(r.I)); I_new ----
        u64 hr0 = 0, hr1 = 0;
        {
            ulonglong2 R0, R1;
            R0 = ld2(RI + rb0 + kb);      R1 = ld2(RI + rb1 + kb);
            ACC2(hr0, whi0, R0);          ACC2(hr1, whi0, R1);
            R0 = ld2(RI + rb0 + kb + 4);  R1 = ld2(RI + rb1 + kb + 4);
            ACC2(hr0, whi1, R0);          ACC2(hr1, whi1, R1);
            R0 = ld2(RI + rb0 + kb + 8);  R1 = ld2(RI + rb1 + kb + 8);
            ACC2(hr0, whi2, R0);          ACC2(hr1, whi2, R1);
            R0 = ld2(RI + rb0 + kb + 12); R1 = ld2(RI + rb1 + kb + 12);
            ACC2(hr0, whi3, R0);          ACC2(hr1, whi3, R1);
        }
        float hv = tanh_f(redu2(f2add(hacc0, hr0), f2add(hacc1, hr1), h, hbi, FULLM));
        float inew = (1.f - z) * Iold + z * (hv * mi);
        In[rbo + d] = inew;
        // prefetch phase-4 c=0 smem weight (only m20 remains in smem for phase 4)
        ulonglong2 qk = WL(20, 0);
        gsync(bar);

        // ---- phase 4 (short): In-chains (reg weights) + acache x m20 ----
        u64 a_i0 = 0, a_i1 = 0, a_a0 = 0, a_a1 = 0;
        u64 ma_i0 = 0, ma_i1 = 0;
        #pragma unroll
        for (int c = 0; c < 4; c++) {
            const int ko = kb + c * 4;
            ulonglong2 Nv0 = ld2(In + rb0 + ko), Nv1 = ld2(In + rb1 + ko);
            ulonglong2 Av0 = { acache[0][2*c], acache[0][2*c+1] };
            ulonglong2 Av1 = { acache[1][2*c], acache[1][2*c+1] };
            ulonglong2 wj = (c == 0) ? w19_0 : (c == 1) ? w19_1 : (c == 2) ? w19_2 : w19_3;
            ulonglong2 wm = (c == 0) ? w22_0 : (c == 1) ? w22_1 : (c == 2) ? w22_2 : w22_3;
            ulonglong2 wk = (c == 0) ? qk : WL(20, c);
            ACC2(a_i0, wj, Nv0);   ACC2(a_i1, wj, Nv1);
            ACC2(a_a0, wk, Av0);   ACC2(a_a1, wk, Av1);
            ACC2(ma_i0, wm, Nv0);  ACC2(ma_i1, wm, Nv1);
        }
        float sA  = redu2(f2add(f2add(a_w0, a_i0), a_a0),
                          f2add(f2add(a_w1, a_i1), a_a1), h, abi, FULLM);
        float sMa = redu2(f2add(ma_w0, ma_i0), f2add(ma_w1, ma_i1), h, amgb, FULLM);
        float anew = tanh_f(sA * sigm(sMa));
        An[rbo + d] = anew;
        gsync(bar);

        // ---- output: actions = phi(A_new); d<4 -> lanes 0..15 of warp 0 of each
        //      group: PARTIAL-WARP branch, so the shfl mask is 0xffff ----
        if (d < Oo) {
            u64 aO0 = 0, aO1 = 0;
            #pragma unroll
            for (int c = 0; c < 4; c++) {
                const int ko = kb + c * 4;
                ulonglong2 pw = ld2(sm + SM_PHI + d * ST + ko);
                ulonglong2 A0 = ld2(An + rb0 + ko), A1 = ld2(An + rb1 + ko);
                ACC2(aO0, pw, A0);
                ACC2(aO1, pw, A1);
            }
            float o = redu2(aO0, aO1, h, phib, 0x0000ffffu);
            p.out[((size_t)t * Bb + gro) * Oo + d] = o;
        }

        // rotate state buffers
        float* tmp;
        tmp = Wc; Wc = Wn; Wn = tmp;
        tmp = Ic; Ic = In; In = tmp;
        tmp = Ac; Ac = An; An = tmp;
    }
    #undef WL
}

extern "C" void kernel_launch(void* const* d_in, const int* in_sizes, int n_in,
                              void* d_out, int out_size) {
    const float* const* in = (const float* const*)d_in;
    const float *obs, *enc_w, *enc_b;
    const float *wW, *wI, *wA, *zW, *zI, *zA, *rW, *rIm, *rA, *hW, *hI, *hA, *aW, *aI, *aA;
    const float *att_w, *att_b, *wmg_w, *wmg_b, *img_w, *img_b, *amg_w, *amg_b;
    const float *z_b, *r_b, *h_b, *a_b, *phi_w, *phi_b;

    if (in_sizes[6] == 2048) {
        obs = in[0]; enc_w = in[1]; enc_b = in[2];
        wW = in[3]; wI = in[4]; wA = in[5];
        att_w = in[6]; att_b = in[7]; wmg_w = in[8]; wmg_b = in[9];
        zW = in[10]; zI = in[11]; zA = in[12]; z_b = in[13];
        rW = in[14]; rIm = in[15]; rA = in[16]; r_b = in[17];
        hW = in[18]; hI = in[19]; hA = in[20]; h_b = in[21];
        img_w = in[22]; img_b = in[23];
        aW = in[24]; aI = in[25]; aA = in[26]; a_b = in[27];
        amg_w = in[28]; amg_b = in[29];
        phi_w = in[30]; phi_b = in[31];
    } else {
        obs = in[0]; enc_w = in[1]; enc_b = in[2];
        wW = in[3]; wI = in[4]; wA = in[5];
        zW = in[6]; zI = in[7]; zA = in[8];
        rW = in[9]; rIm = in[10]; rA = in[11];
        hW = in[12]; hI = in[13]; hA = in[14];
        aW = in[15]; aI = in[16]; aA = in[17];
        att_w = in[18]; att_b = in[19];
        wmg_w = in[20]; wmg_b = in[21];
        img_w = in[22]; img_b = in[23];
        amg_w = in[24]; amg_b = in[25];
        z_b = in[26]; r_b = in[27]; h_b = in[28]; a_b = in[29];
        phi_w = in[30]; phi_b = in[31];
    }

    Params p;
    p.obs = obs; p.enc_w = enc_w;
    const float* sq[NMAT] = {
        wW, wI, wA,
        att_w, att_w + 32,
        wmg_w, wmg_w + 32,
        zW, zI, zA,
        rW, rIm, rA,
        hW, hI, hA,
        img_w, img_w + 32,
        aW, aI, aA,
        amg_w, amg_w + 32
    };
    const int rs[NMAT] = {
        32, 32, 32,
        64, 64,
        64, 64,
        32, 32, 32,
        32, 32, 32,
        32, 32, 32,
        64, 64,
        32, 32, 32,
        64, 64
    };
    for (int i = 0; i < NMAT; i++) { p.sq[i] = sq[i]; p.rs[i] = rs[i]; }
    const float* bv[9] = { att_b, wmg_b, img_b, amg_b, z_b, r_b, h_b, a_b, enc_b };
    for (int i = 0; i < 9; i++) p.bv[i] = bv[i];
    p.phi_w = phi_w; p.phi_b = phi_b;
    p.out = (float*)d_out;

    const int smemBytes = SM_TOT * (int)sizeof(float);
    cudaFuncSetAttribute(anima_kernel,
                         cudaFuncAttributeMaxDynamicSharedMemorySize, smemBytes);
    anima_kernel<<<Bb / ROWS, NTHR, smemBytes>>>(p);
}